// round 1
// baseline (speedup 1.0000x reference)
#include <cuda_runtime.h>
#include <math.h>

// Problem constants
#define C_MODEL 1024
#define N_HEAD  16
#define DK      64
#define T_SEQ   1024
#define N_BATCH 8
#define M_ROWS  (N_BATCH * T_SEQ)   // 8192

// Scratch (device globals; allocation-free per harness rules)
__device__ float g_q[N_BATCH * N_HEAD * T_SEQ * DK];   // [B,H,T,dk]
__device__ float g_k[N_BATCH * N_HEAD * T_SEQ * DK];
__device__ float g_v[N_BATCH * N_HEAD * T_SEQ * DK];
__device__ float g_y[M_ROWS * C_MODEL];                // attention out, [B*T, C]

// ---------------------------------------------------------------------------
// SGEMM: C[M=8192, N] = A[8192,1024] @ B[1024,N], 128x128x16 tiles, 256 thr,
// 8x8 per-thread micro-tile.
// EPI=0: plain row-major store into C.
// EPI=1: scatter into g_q/g_k/g_v in [B,H,T,dk] layout (QKV split + head fold).
// AFY  : read A from g_y instead of the pointer arg (proj GEMM).
// ---------------------------------------------------------------------------
template <int N, int EPI, bool AFY>
__global__ void __launch_bounds__(256) sgemm_kernel(const float* __restrict__ A,
                                                    const float* __restrict__ B,
                                                    float* __restrict__ C) {
    constexpr int K = 1024;
    __shared__ float As[16][132];   // A^T tile: As[k][m]
    __shared__ float Bs[16][132];   // Bs[k][n]

    const float* Ap = AFY ? g_y : A;

    const int tid = threadIdx.x;
    const int tx  = tid & 15;       // 0..15 -> 8 output cols
    const int ty  = tid >> 4;       // 0..15 -> 8 output rows
    const int row0 = blockIdx.y * 128;
    const int col0 = blockIdx.x * 128;

    // loader mapping
    const int ar = tid >> 2;            // 0..63 (A row within tile, +64 second pass)
    const int ak = (tid & 3) << 2;      // 0,4,8,12
    const int br = tid >> 5;            // 0..7  (B row within tile, +8 second pass)
    const int bc = (tid & 31) << 2;     // 0..124

    float acc[8][8];
#pragma unroll
    for (int i = 0; i < 8; i++)
#pragma unroll
        for (int j = 0; j < 8; j++) acc[i][j] = 0.f;

    for (int k0 = 0; k0 < K; k0 += 16) {
        // load A tile (transposed into smem)
#pragma unroll
        for (int p = 0; p < 2; p++) {
            const int r = ar + p * 64;
            float4 v = *(const float4*)(Ap + (size_t)(row0 + r) * K + k0 + ak);
            As[ak + 0][r] = v.x;
            As[ak + 1][r] = v.y;
            As[ak + 2][r] = v.z;
            As[ak + 3][r] = v.w;
        }
        // load B tile
#pragma unroll
        for (int p = 0; p < 2; p++) {
            const int r = br + p * 8;
            float4 v = *(const float4*)(B + (size_t)(k0 + r) * N + col0 + bc);
            *(float4*)&Bs[r][bc] = v;
        }
        __syncthreads();

#pragma unroll
        for (int kk = 0; kk < 16; kk++) {
            float4 a0 = *(const float4*)&As[kk][ty * 8];
            float4 a1 = *(const float4*)&As[kk][ty * 8 + 4];
            float4 b0 = *(const float4*)&Bs[kk][tx * 8];
            float4 b1 = *(const float4*)&Bs[kk][tx * 8 + 4];
            float a[8] = {a0.x, a0.y, a0.z, a0.w, a1.x, a1.y, a1.z, a1.w};
            float b[8] = {b0.x, b0.y, b0.z, b0.w, b1.x, b1.y, b1.z, b1.w};
#pragma unroll
            for (int i = 0; i < 8; i++)
#pragma unroll
                for (int j = 0; j < 8; j++) acc[i][j] += a[i] * b[j];
        }
        __syncthreads();
    }

    // epilogue
    const int gn0 = col0 + tx * 8;
#pragma unroll
    for (int i = 0; i < 8; i++) {
        const int gm = row0 + ty * 8 + i;
        if constexpr (EPI == 0) {
            float4 v0 = make_float4(acc[i][0], acc[i][1], acc[i][2], acc[i][3]);
            float4 v1 = make_float4(acc[i][4], acc[i][5], acc[i][6], acc[i][7]);
            *(float4*)&C[(size_t)gm * N + gn0]     = v0;
            *(float4*)&C[(size_t)gm * N + gn0 + 4] = v1;
        } else {
            // qkv scatter: gn in [0,3072); part=gn/1024, head=(gn%1024)/64, d=(gn%64)
            // gn0 is a multiple of 8, so all 8 cols share part/head; d contiguous.
            const int b_   = gm >> 10;
            const int t_   = gm & 1023;
            const int part = gn0 >> 10;
            const int rem  = gn0 & 1023;
            const int h_   = rem >> 6;
            const int d0   = rem & 63;
            float* dst = (part == 0) ? g_q : (part == 1) ? g_k : g_v;
            const size_t base = ((((size_t)b_ * N_HEAD + h_) * T_SEQ) + t_) * DK + d0;
            float4 v0 = make_float4(acc[i][0], acc[i][1], acc[i][2], acc[i][3]);
            float4 v1 = make_float4(acc[i][4], acc[i][5], acc[i][6], acc[i][7]);
            *(float4*)&dst[base]     = v0;
            *(float4*)&dst[base + 4] = v1;
        }
    }
}

// ---------------------------------------------------------------------------
// Flash-style causal attention.
// Grid: (16 q-tiles, 128 b*h). Block: 256 threads.
// Per CTA: Q tile [64,dk=64]; loop over causal K/V tiles of 64 rows.
// Q,K stored d-major in smem (float4 fragment loads); V row-major; S tile
// pitch 65 (conflict-free row-serial softmax). Online softmax, O in regs.
// ---------------------------------------------------------------------------
__global__ void __launch_bounds__(256) attn_kernel() {
    extern __shared__ float sm[];
    float* Qst = sm;                    // [d][i], pitch 68  (64*68)
    float* Kst = Qst + 64 * 68;         // [d][j], pitch 68
    float* Vs  = Kst + 64 * 68;         // [k][j], pitch 68
    float* Ss  = Vs  + 64 * 68;         // [i][j], pitch 65  (64*65)
    float* m_s = Ss + 64 * 65;          // running max  [64]
    float* l_s = m_s + 64;              // running sum  [64]
    float* c_s = l_s + 64;              // rescale      [64]

    const int qt  = blockIdx.x;         // q tile 0..15
    const int bh  = blockIdx.y;         // 0..127
    const int tid = threadIdx.x;
    const int tx  = tid & 15;
    const int ty  = tid >> 4;
    const int i0  = ty << 2;            // 4 S-rows / O-rows
    const int j0  = tx << 2;            // 4 S-cols / O-cols

    const float* Qg = g_q + (size_t)bh * (T_SEQ * DK);
    const float* Kg = g_k + (size_t)bh * (T_SEQ * DK);
    const float* Vg = g_v + (size_t)bh * (T_SEQ * DK);

    // load Q tile, transposed to d-major
#pragma unroll
    for (int e = tid; e < 64 * 64; e += 256) {
        const int i = e >> 6, d = e & 63;
        Qst[d * 68 + i] = Qg[(qt * 64 + i) * 64 + d];
    }
    if (tid < 64) { m_s[tid] = -3.0e38f; l_s[tid] = 0.f; }

    float O[4][4] = {};

    for (int kt = 0; kt <= qt; kt++) {
        __syncthreads();   // previous iter's consumers done before reload
#pragma unroll
        for (int e = tid; e < 64 * 64; e += 256) {
            const int i = e >> 6, d = e & 63;
            const float kv = Kg[(kt * 64 + i) * 64 + d];
            const float vv = Vg[(kt * 64 + i) * 64 + d];
            Kst[d * 68 + i] = kv;   // transposed
            Vs[i * 68 + d]  = vv;   // row-major
        }
        __syncthreads();

        // S = (Q K^T) * 1/sqrt(dk)
        float s[4][4] = {};
#pragma unroll 16
        for (int d = 0; d < 64; d++) {
            float4 qf = *(const float4*)&Qst[d * 68 + i0];
            float4 kf = *(const float4*)&Kst[d * 68 + j0];
            const float qa[4] = {qf.x, qf.y, qf.z, qf.w};
            const float kb[4] = {kf.x, kf.y, kf.z, kf.w};
#pragma unroll
            for (int r = 0; r < 4; r++)
#pragma unroll
                for (int c = 0; c < 4; c++) s[r][c] += qa[r] * kb[c];
        }
        const bool diag = (kt == qt);
#pragma unroll
        for (int r = 0; r < 4; r++)
#pragma unroll
            for (int c = 0; c < 4; c++) {
                float v = s[r][c] * 0.125f;
                if (diag && (j0 + c > i0 + r)) v = -3.0e38f;  // exp -> exactly 0
                Ss[(i0 + r) * 65 + (j0 + c)] = v;
            }
        __syncthreads();

        // online softmax: one thread per row (pitch-65 -> conflict-free)
        if (tid < 64) {
            float* row = &Ss[tid * 65];
            float rm = -3.0e38f;
#pragma unroll 8
            for (int j = 0; j < 64; j++) rm = fmaxf(rm, row[j]);
            const float mold = m_s[tid];
            const float mnew = fmaxf(mold, rm);
            const float sc   = __expf(mold - mnew);
            float sum = 0.f;
#pragma unroll 8
            for (int j = 0; j < 64; j++) {
                const float p = __expf(row[j] - mnew);
                row[j] = p;
                sum += p;
            }
            m_s[tid] = mnew;
            l_s[tid] = l_s[tid] * sc + sum;
            c_s[tid] = sc;
        }
        __syncthreads();

        // O = O*scale + P @ V
        float cr[4];
#pragma unroll
        for (int r = 0; r < 4; r++) cr[r] = c_s[i0 + r];
#pragma unroll
        for (int r = 0; r < 4; r++)
#pragma unroll
            for (int c = 0; c < 4; c++) O[r][c] *= cr[r];

#pragma unroll 8
        for (int k = 0; k < 64; k++) {
            float4 vf = *(const float4*)&Vs[k * 68 + j0];
            const float p0 = Ss[(i0 + 0) * 65 + k];
            const float p1 = Ss[(i0 + 1) * 65 + k];
            const float p2 = Ss[(i0 + 2) * 65 + k];
            const float p3 = Ss[(i0 + 3) * 65 + k];
            O[0][0] += p0 * vf.x; O[0][1] += p0 * vf.y; O[0][2] += p0 * vf.z; O[0][3] += p0 * vf.w;
            O[1][0] += p1 * vf.x; O[1][1] += p1 * vf.y; O[1][2] += p1 * vf.z; O[1][3] += p1 * vf.w;
            O[2][0] += p2 * vf.x; O[2][1] += p2 * vf.y; O[2][2] += p2 * vf.z; O[2][3] += p2 * vf.w;
            O[3][0] += p3 * vf.x; O[3][1] += p3 * vf.y; O[3][2] += p3 * vf.z; O[3][3] += p3 * vf.w;
        }
    }

    // finalize: divide by l, write y[b, t, h*64+d]  ([B,T,C] row-major)
    const int b_ = bh >> 4, h_ = bh & 15;
#pragma unroll
    for (int r = 0; r < 4; r++) {
        const float inv = 1.0f / l_s[i0 + r];
        const int t = qt * 64 + i0 + r;
        float4 o = make_float4(O[r][0] * inv, O[r][1] * inv, O[r][2] * inv, O[r][3] * inv);
        *(float4*)&g_y[((size_t)(b_ * T_SEQ + t)) * C_MODEL + h_ * DK + j0] = o;
    }
}

// ---------------------------------------------------------------------------

extern "C" void kernel_launch(void* const* d_in, const int* in_sizes, int n_in,
                              void* d_out, int out_size) {
    const float* x     = (const float*)d_in[0];   // [8,1024,1024]
    const float* wqkv  = (const float*)d_in[1];   // [1024,3072]
    const float* wproj = (const float*)d_in[2];   // [1024,1024]
    float* out = (float*)d_out;                   // [8,1024,1024]

    const int ATTN_SMEM = (3 * 64 * 68 + 64 * 65 + 3 * 64) * 4;  // 69632 B
    cudaFuncSetAttribute(attn_kernel,
                         cudaFuncAttributeMaxDynamicSharedMemorySize, ATTN_SMEM);

    dim3 blk(256);
    // 1) QKV projection, scattered into [B,H,T,dk] Q/K/V
    sgemm_kernel<3072, 1, false><<<dim3(3072 / 128, M_ROWS / 128), blk>>>(x, wqkv, nullptr);
    // 2) causal attention -> g_y [B*T, C]
    attn_kernel<<<dim3(T_SEQ / 64, N_BATCH * N_HEAD), blk, ATTN_SMEM>>>();
    // 3) output projection
    sgemm_kernel<1024, 0, true><<<dim3(1024 / 128, M_ROWS / 128), blk>>>(nullptr, wproj, out);
}

// round 3
// speedup vs baseline: 1.6358x; 1.6358x over previous
#include <cuda_runtime.h>
#include <cuda_bf16.h>
#include <cstdint>
#include <math.h>

// Problem constants
#define C_MODEL 1024
#define N_HEAD  16
#define DK      64
#define T_SEQ   1024
#define N_BATCH 8
#define M_ROWS  (N_BATCH * T_SEQ)   // 8192

// ------------------------- scratch (device globals) -------------------------
__device__ float g_q[N_BATCH * N_HEAD * T_SEQ * DK];   // [B,H,T,dk]
__device__ float g_k[N_BATCH * N_HEAD * T_SEQ * DK];
__device__ float g_v[N_BATCH * N_HEAD * T_SEQ * DK];
__device__ float g_y[M_ROWS * C_MODEL];                // attention out, [B*T, C]

__device__ __align__(256) __nv_bfloat16 g_xh[M_ROWS * C_MODEL];
__device__ __align__(256) __nv_bfloat16 g_xl[M_ROWS * C_MODEL];
__device__ __align__(256) __nv_bfloat16 g_yh[M_ROWS * C_MODEL];
__device__ __align__(256) __nv_bfloat16 g_yl[M_ROWS * C_MODEL];
__device__ __align__(256) __nv_bfloat16 g_wqh[3 * C_MODEL * C_MODEL];  // [3072,1024] (W^T)
__device__ __align__(256) __nv_bfloat16 g_wql[3 * C_MODEL * C_MODEL];
__device__ __align__(256) __nv_bfloat16 g_wph[C_MODEL * C_MODEL];      // [1024,1024] (W^T)
__device__ __align__(256) __nv_bfloat16 g_wpl[C_MODEL * C_MODEL];

// ------------------------- PTX helpers (portable ISA only) -------------------------
__device__ __forceinline__ uint32_t smem_u32(const void* p) {
    uint32_t a;
    asm("{ .reg .u64 t; cvta.to.shared.u64 t, %1; cvt.u32.u64 %0, t; }" : "=r"(a) : "l"(p));
    return a;
}

__device__ __forceinline__ void cpasync16(uint32_t dst, const void* src) {
    asm volatile("cp.async.cg.shared.global [%0], [%1], 16;" :: "r"(dst), "l"(src));
}
#define CP_COMMIT() asm volatile("cp.async.commit_group;" ::: "memory")
#define CP_WAIT(n)  asm volatile("cp.async.wait_group %0;" :: "n"(n) : "memory")

__device__ __forceinline__ void ldsm4(uint32_t& r0, uint32_t& r1, uint32_t& r2, uint32_t& r3,
                                      uint32_t addr) {
    asm volatile("ldmatrix.sync.aligned.m8n8.x4.shared.b16 {%0,%1,%2,%3}, [%4];"
                 : "=r"(r0), "=r"(r1), "=r"(r2), "=r"(r3) : "r"(addr));
}
__device__ __forceinline__ void ldsm2(uint32_t& r0, uint32_t& r1, uint32_t addr) {
    asm volatile("ldmatrix.sync.aligned.m8n8.x2.shared.b16 {%0,%1}, [%2];"
                 : "=r"(r0), "=r"(r1) : "r"(addr));
}
__device__ __forceinline__ void mma16816(float* c, uint32_t a0, uint32_t a1, uint32_t a2,
                                         uint32_t a3, uint32_t b0, uint32_t b1) {
    asm volatile(
        "mma.sync.aligned.m16n8k16.row.col.f32.bf16.bf16.f32 "
        "{%0,%1,%2,%3}, {%4,%5,%6,%7}, {%8,%9}, {%0,%1,%2,%3};"
        : "+f"(c[0]), "+f"(c[1]), "+f"(c[2]), "+f"(c[3])
        : "r"(a0), "r"(a1), "r"(a2), "r"(a3), "r"(b0), "r"(b1));
}

// ------------------------- conversion kernels -------------------------
__global__ void split_kernel(const float* __restrict__ in,
                             __nv_bfloat16* __restrict__ hi,
                             __nv_bfloat16* __restrict__ lo, int n4) {
    int i = blockIdx.x * blockDim.x + threadIdx.x;
    if (i >= n4) return;
    float4 v = ((const float4*)in)[i];
    __nv_bfloat16 h0 = __float2bfloat16(v.x), h1 = __float2bfloat16(v.y);
    __nv_bfloat16 h2 = __float2bfloat16(v.z), h3 = __float2bfloat16(v.w);
    __nv_bfloat16 l0 = __float2bfloat16(v.x - __bfloat162float(h0));
    __nv_bfloat16 l1 = __float2bfloat16(v.y - __bfloat162float(h1));
    __nv_bfloat16 l2 = __float2bfloat16(v.z - __bfloat162float(h2));
    __nv_bfloat16 l3 = __float2bfloat16(v.w - __bfloat162float(h3));
    ((__nv_bfloat162*)hi)[2 * i]     = __nv_bfloat162(h0, h1);
    ((__nv_bfloat162*)hi)[2 * i + 1] = __nv_bfloat162(h2, h3);
    ((__nv_bfloat162*)lo)[2 * i]     = __nv_bfloat162(l0, l1);
    ((__nv_bfloat162*)lo)[2 * i + 1] = __nv_bfloat162(l2, l3);
}

// W [K, N] fp32 row-major -> Th/Tl [N, K] bf16 (transposed + split)
__global__ void transpose_split(const float* __restrict__ W,
                                __nv_bfloat16* __restrict__ Th,
                                __nv_bfloat16* __restrict__ Tl, int K, int N) {
    __shared__ float t[32][33];
    const int bx = blockIdx.x * 32;   // n offset
    const int by = blockIdx.y * 32;   // k offset
    const int x = threadIdx.x, y = threadIdx.y;
#pragma unroll
    for (int j = 0; j < 32; j += 8)
        t[y + j][x] = W[(size_t)(by + y + j) * N + bx + x];
    __syncthreads();
#pragma unroll
    for (int j = 0; j < 32; j += 8) {
        float v = t[x][y + j];        // = W[by+x][bx+y+j]
        __nv_bfloat16 h = __float2bfloat16(v);
        __nv_bfloat16 l = __float2bfloat16(v - __bfloat162float(h));
        size_t o = (size_t)(bx + y + j) * K + by + x;
        Th[o] = h; Tl[o] = l;
    }
}

// ------------------------- mma.sync GEMM -------------------------
// C[8192, NTOT] = A[8192,1024] @ BT[NTOT,1024]^T, bf16 hi/lo x 3 products, fp32 accum.
// CTA tile 128(M) x 256(N) x 32(K-stage); 256 threads = 8 warps (2M x 4N), warp 64x64.
// smem rows padded to 80B (32 bf16 + 16B pad) -> conflict-free ldmatrix.
#define GT_M 128
#define GT_N 256
#define GT_K 32
#define G_NSTAGE 32                 // 1024 / 32
#define ROWB 80
#define OFF_AH 0
#define OFF_AL (128 * ROWB)         // 10240
#define OFF_BH (2 * 128 * ROWB)     // 20480
#define OFF_BL (OFF_BH + 256 * ROWB)// 40960
#define STAGE_B (OFF_BL + 256 * ROWB) // 61440
#define GEMM_SMEM (2 * STAGE_B)     // 122880

template <int NTOT, int EPI>
__global__ void __launch_bounds__(256) mma_gemm(const __nv_bfloat16* __restrict__ Ah_,
                                                const __nv_bfloat16* __restrict__ Al_,
                                                const __nv_bfloat16* __restrict__ Bh_,
                                                const __nv_bfloat16* __restrict__ Bl_,
                                                float* __restrict__ C) {
    extern __shared__ char sm[];
    const uint32_t sbase = smem_u32(sm);
    const int tid  = threadIdx.x;
    const int lane = tid & 31;
    const int wid  = tid >> 5;
    const int wm   = wid & 1;          // 0..1
    const int wn   = wid >> 1;         // 0..3
    const int row0 = blockIdx.y * GT_M;
    const int col0 = blockIdx.x * GT_N;

    float acc[4][8][4];
#pragma unroll
    for (int i = 0; i < 4; i++)
#pragma unroll
        for (int j = 0; j < 8; j++)
#pragma unroll
            for (int k = 0; k < 4; k++) acc[i][j][k] = 0.f;

    // loader lambda: 12 cp.async of 16B per thread per stage
    auto load_stage = [&](int kt, int buf) {
        const uint32_t sa = sbase + buf * STAGE_B;
        const int kcol = kt * GT_K;
#pragma unroll
        for (int p = 0; p < 2; p++) {
            const int i = p * 256 + tid, r = i >> 2, c = i & 3;
            cpasync16(sa + OFF_AH + r * ROWB + c * 16,
                      Ah_ + (size_t)(row0 + r) * 1024 + kcol + c * 8);
        }
#pragma unroll
        for (int p = 0; p < 2; p++) {
            const int i = p * 256 + tid, r = i >> 2, c = i & 3;
            cpasync16(sa + OFF_AL + r * ROWB + c * 16,
                      Al_ + (size_t)(row0 + r) * 1024 + kcol + c * 8);
        }
#pragma unroll
        for (int p = 0; p < 4; p++) {
            const int i = p * 256 + tid, r = i >> 2, c = i & 3;
            cpasync16(sa + OFF_BH + r * ROWB + c * 16,
                      Bh_ + (size_t)(col0 + r) * 1024 + kcol + c * 8);
        }
#pragma unroll
        for (int p = 0; p < 4; p++) {
            const int i = p * 256 + tid, r = i >> 2, c = i & 3;
            cpasync16(sa + OFF_BL + r * ROWB + c * 16,
                      Bl_ + (size_t)(col0 + r) * 1024 + kcol + c * 8);
        }
        CP_COMMIT();
    };

    // per-thread ldmatrix base addresses (within a stage buffer)
    const uint32_t a_base = OFF_AH + (wm * 64 + (lane & 15)) * ROWB + (lane >> 4) * 16;
    const uint32_t b_base = OFF_BH + (wn * 64 + (lane & 7)) * ROWB + ((lane >> 3) & 1) * 16;

    load_stage(0, 0);
    load_stage(1, 1);

    for (int kt = 0; kt < G_NSTAGE; kt++) {
        if (kt == G_NSTAGE - 1) { CP_WAIT(0); } else { CP_WAIT(1); }
        __syncthreads();

        const uint32_t sa = sbase + (kt & 1) * STAGE_B;
#pragma unroll
        for (int kk = 0; kk < 2; kk++) {
            const uint32_t koff = kk * 32;   // 16 bf16 = 32B per k16 step
            uint32_t ah[4][4], bh[8][2];
#pragma unroll
            for (int mt = 0; mt < 4; mt++)
                ldsm4(ah[mt][0], ah[mt][1], ah[mt][2], ah[mt][3],
                      sa + a_base + mt * 16 * ROWB + koff);
#pragma unroll
            for (int nt = 0; nt < 8; nt++)
                ldsm2(bh[nt][0], bh[nt][1], sa + b_base + nt * 8 * ROWB + koff);
#pragma unroll
            for (int mt = 0; mt < 4; mt++)
#pragma unroll
                for (int nt = 0; nt < 8; nt++)
                    mma16816(acc[mt][nt], ah[mt][0], ah[mt][1], ah[mt][2], ah[mt][3],
                             bh[nt][0], bh[nt][1]);

            uint32_t al[4][4];
#pragma unroll
            for (int mt = 0; mt < 4; mt++)
                ldsm4(al[mt][0], al[mt][1], al[mt][2], al[mt][3],
                      sa + a_base + (OFF_AL - OFF_AH) + mt * 16 * ROWB + koff);
#pragma unroll
            for (int mt = 0; mt < 4; mt++)
#pragma unroll
                for (int nt = 0; nt < 8; nt++)
                    mma16816(acc[mt][nt], al[mt][0], al[mt][1], al[mt][2], al[mt][3],
                             bh[nt][0], bh[nt][1]);

            uint32_t bl[8][2];
#pragma unroll
            for (int nt = 0; nt < 8; nt++)
                ldsm2(bl[nt][0], bl[nt][1],
                      sa + b_base + (OFF_BL - OFF_BH) + nt * 8 * ROWB + koff);
#pragma unroll
            for (int mt = 0; mt < 4; mt++)
#pragma unroll
                for (int nt = 0; nt < 8; nt++)
                    mma16816(acc[mt][nt], ah[mt][0], ah[mt][1], ah[mt][2], ah[mt][3],
                             bl[nt][0], bl[nt][1]);
        }
        __syncthreads();
        if (kt + 2 < G_NSTAGE) load_stage(kt + 2, kt & 1);
    }

    // epilogue: c-frag direct stores
    const int rbase = lane >> 2;       // 0..7
    const int cpair = (lane & 3) * 2;  // 0,2,4,6
#pragma unroll
    for (int mt = 0; mt < 4; mt++) {
#pragma unroll
        for (int nt = 0; nt < 8; nt++) {
            const float* c = acc[mt][nt];
            const int gcol = col0 + wn * 64 + nt * 8 + cpair;
            const int r1 = row0 + wm * 64 + mt * 16 + rbase;
            const int r2 = r1 + 8;
            if constexpr (EPI == 0) {
                *(float2*)&C[(size_t)r1 * NTOT + gcol] = make_float2(c[0], c[1]);
                *(float2*)&C[(size_t)r2 * NTOT + gcol] = make_float2(c[2], c[3]);
            } else {
                const int part = gcol >> 10;
                const int rem  = gcol & 1023;
                const int h = rem >> 6, d = rem & 63;
                float* dst = (part == 0) ? g_q : (part == 1) ? g_k : g_v;
#pragma unroll
                for (int hh = 0; hh < 2; hh++) {
                    const int gr = hh ? r2 : r1;
                    const int b_ = gr >> 10, t_ = gr & 1023;
                    const size_t o = ((((size_t)b_ * N_HEAD + h) * T_SEQ) + t_) * DK + d;
                    *(float2*)&dst[o] = make_float2(c[hh * 2], c[hh * 2 + 1]);
                }
            }
        }
    }
}

// ------------------------- flash-style causal attention (unchanged) -------------------------
__global__ void __launch_bounds__(256) attn_kernel() {
    extern __shared__ float smf[];
    float* Qst = smf;
    float* Kst = Qst + 64 * 68;
    float* Vs  = Kst + 64 * 68;
    float* Ss  = Vs  + 64 * 68;
    float* m_s = Ss + 64 * 65;
    float* l_s = m_s + 64;
    float* c_s = l_s + 64;

    const int qt  = blockIdx.x;
    const int bh  = blockIdx.y;
    const int tid = threadIdx.x;
    const int tx  = tid & 15;
    const int ty  = tid >> 4;
    const int i0  = ty << 2;
    const int j0  = tx << 2;

    const float* Qg = g_q + (size_t)bh * (T_SEQ * DK);
    const float* Kg = g_k + (size_t)bh * (T_SEQ * DK);
    const float* Vg = g_v + (size_t)bh * (T_SEQ * DK);

#pragma unroll
    for (int e = tid; e < 64 * 64; e += 256) {
        const int i = e >> 6, d = e & 63;
        Qst[d * 68 + i] = Qg[(qt * 64 + i) * 64 + d];
    }
    if (tid < 64) { m_s[tid] = -3.0e38f; l_s[tid] = 0.f; }

    float O[4][4] = {};

    for (int kt = 0; kt <= qt; kt++) {
        __syncthreads();
#pragma unroll
        for (int e = tid; e < 64 * 64; e += 256) {
            const int i = e >> 6, d = e & 63;
            Kst[d * 68 + i] = Kg[(kt * 64 + i) * 64 + d];
            Vs[i * 68 + d]  = Vg[(kt * 64 + i) * 64 + d];
        }
        __syncthreads();

        float s[4][4] = {};
#pragma unroll 16
        for (int d = 0; d < 64; d++) {
            float4 qf = *(const float4*)&Qst[d * 68 + i0];
            float4 kf = *(const float4*)&Kst[d * 68 + j0];
            const float qa[4] = {qf.x, qf.y, qf.z, qf.w};
            const float kb[4] = {kf.x, kf.y, kf.z, kf.w};
#pragma unroll
            for (int r = 0; r < 4; r++)
#pragma unroll
                for (int c = 0; c < 4; c++) s[r][c] += qa[r] * kb[c];
        }
        const bool diag = (kt == qt);
#pragma unroll
        for (int r = 0; r < 4; r++)
#pragma unroll
            for (int c = 0; c < 4; c++) {
                float v = s[r][c] * 0.125f;
                if (diag && (j0 + c > i0 + r)) v = -3.0e38f;
                Ss[(i0 + r) * 65 + (j0 + c)] = v;
            }
        __syncthreads();

        if (tid < 64) {
            float* row = &Ss[tid * 65];
            float rm = -3.0e38f;
#pragma unroll 8
            for (int j = 0; j < 64; j++) rm = fmaxf(rm, row[j]);
            const float mold = m_s[tid];
            const float mnew = fmaxf(mold, rm);
            const float sc   = __expf(mold - mnew);
            float sum = 0.f;
#pragma unroll 8
            for (int j = 0; j < 64; j++) {
                const float p = __expf(row[j] - mnew);
                row[j] = p;
                sum += p;
            }
            m_s[tid] = mnew;
            l_s[tid] = l_s[tid] * sc + sum;
            c_s[tid] = sc;
        }
        __syncthreads();

        float cr[4];
#pragma unroll
        for (int r = 0; r < 4; r++) cr[r] = c_s[i0 + r];
#pragma unroll
        for (int r = 0; r < 4; r++)
#pragma unroll
            for (int c = 0; c < 4; c++) O[r][c] *= cr[r];

#pragma unroll 8
        for (int k = 0; k < 64; k++) {
            float4 vf = *(const float4*)&Vs[k * 68 + j0];
            const float p0 = Ss[(i0 + 0) * 65 + k];
            const float p1 = Ss[(i0 + 1) * 65 + k];
            const float p2 = Ss[(i0 + 2) * 65 + k];
            const float p3 = Ss[(i0 + 3) * 65 + k];
            O[0][0] += p0 * vf.x; O[0][1] += p0 * vf.y; O[0][2] += p0 * vf.z; O[0][3] += p0 * vf.w;
            O[1][0] += p1 * vf.x; O[1][1] += p1 * vf.y; O[1][2] += p1 * vf.z; O[1][3] += p1 * vf.w;
            O[2][0] += p2 * vf.x; O[2][1] += p2 * vf.y; O[2][2] += p2 * vf.z; O[2][3] += p2 * vf.w;
            O[3][0] += p3 * vf.x; O[3][1] += p3 * vf.y; O[3][2] += p3 * vf.z; O[3][3] += p3 * vf.w;
        }
    }

    const int b_ = bh >> 4, h_ = bh & 15;
#pragma unroll
    for (int r = 0; r < 4; r++) {
        const float inv = 1.0f / l_s[i0 + r];
        const int t = qt * 64 + i0 + r;
        float4 o = make_float4(O[r][0] * inv, O[r][1] * inv, O[r][2] * inv, O[r][3] * inv);
        *(float4*)&g_y[((size_t)(b_ * T_SEQ + t)) * C_MODEL + h_ * DK + j0] = o;
    }
}

// ---------------------------------------------------------------------------

extern "C" void kernel_launch(void* const* d_in, const int* in_sizes, int n_in,
                              void* d_out, int out_size) {
    const float* x     = (const float*)d_in[0];   // [8,1024,1024]
    const float* wqkv  = (const float*)d_in[1];   // [1024,3072]
    const float* wproj = (const float*)d_in[2];   // [1024,1024]
    float* out = (float*)d_out;                   // [8,1024,1024]

    const int ATTN_SMEM = (3 * 64 * 68 + 64 * 65 + 3 * 64) * 4;  // 69632 B
    cudaFuncSetAttribute(attn_kernel,
                         cudaFuncAttributeMaxDynamicSharedMemorySize, ATTN_SMEM);
    cudaFuncSetAttribute(mma_gemm<3072, 1>,
                         cudaFuncAttributeMaxDynamicSharedMemorySize, GEMM_SMEM);
    cudaFuncSetAttribute(mma_gemm<1024, 0>,
                         cudaFuncAttributeMaxDynamicSharedMemorySize, GEMM_SMEM);

    __nv_bfloat16 *xh, *xl, *yh, *yl, *wqh, *wql, *wph, *wpl;
    cudaGetSymbolAddress((void**)&xh,  g_xh);
    cudaGetSymbolAddress((void**)&xl,  g_xl);
    cudaGetSymbolAddress((void**)&yh,  g_yh);
    cudaGetSymbolAddress((void**)&yl,  g_yl);
    cudaGetSymbolAddress((void**)&wqh, g_wqh);
    cudaGetSymbolAddress((void**)&wql, g_wql);
    cudaGetSymbolAddress((void**)&wph, g_wph);
    cudaGetSymbolAddress((void**)&wpl, g_wpl);
    float* y_dev;
    cudaGetSymbolAddress((void**)&y_dev, g_y);

    // 1) fp32 -> bf16 hi/lo conversions (weights also transposed to [N, K])
    split_kernel<<<(M_ROWS * C_MODEL / 4 + 255) / 256, 256>>>(x, xh, xl, M_ROWS * C_MODEL / 4);
    transpose_split<<<dim3(3072 / 32, 1024 / 32), dim3(32, 8)>>>(wqkv, wqh, wql, 1024, 3072);
    transpose_split<<<dim3(1024 / 32, 1024 / 32), dim3(32, 8)>>>(wproj, wph, wpl, 1024, 1024);

    // 2) QKV projection via mma.sync, scattered into [B,H,T,dk]
    mma_gemm<3072, 1><<<dim3(3072 / GT_N, M_ROWS / GT_M), 256, GEMM_SMEM>>>(
        xh, xl, wqh, wql, nullptr);

    // 3) causal attention -> g_y
    attn_kernel<<<dim3(T_SEQ / 64, N_BATCH * N_HEAD), 256, ATTN_SMEM>>>();

    // 4) split attention output, then output projection
    split_kernel<<<(M_ROWS * C_MODEL / 4 + 255) / 256, 256>>>(y_dev, yh, yl, M_ROWS * C_MODEL / 4);
    mma_gemm<1024, 0><<<dim3(1024 / GT_N, M_ROWS / GT_M), 256, GEMM_SMEM>>>(
        yh, yl, wph, wpl, out);
}

// round 4
// speedup vs baseline: 2.5974x; 1.5878x over previous
#include <cuda_runtime.h>
#include <cuda_bf16.h>
#include <cstdint>
#include <math.h>

// Problem constants
#define C_MODEL 1024
#define N_HEAD  16
#define DK      64
#define T_SEQ   1024
#define N_BATCH 8
#define M_ROWS  (N_BATCH * T_SEQ)   // 8192
#define QKD     (N_BATCH * N_HEAD * T_SEQ * DK)   // 8388608

// ------------------------- scratch (device globals) -------------------------
__device__ __align__(256) __nv_bfloat16 g_xh[M_ROWS * C_MODEL];
__device__ __align__(256) __nv_bfloat16 g_xl[M_ROWS * C_MODEL];
__device__ __align__(256) __nv_bfloat16 g_qh[QKD];   // [B,H,T,dk], pre-scaled by 0.125
__device__ __align__(256) __nv_bfloat16 g_ql[QKD];
__device__ __align__(256) __nv_bfloat16 g_kh[QKD];   // [B,H,T,dk]
__device__ __align__(256) __nv_bfloat16 g_kl[QKD];
__device__ __align__(256) __nv_bfloat16 g_vth[QKD];  // [B,H,dk,T]  (V transposed)
__device__ __align__(256) __nv_bfloat16 g_vtl[QKD];
__device__ __align__(256) __nv_bfloat16 g_yh[M_ROWS * C_MODEL];   // attn out
__device__ __align__(256) __nv_bfloat16 g_yl[M_ROWS * C_MODEL];
__device__ __align__(256) __nv_bfloat16 g_wqh[3 * C_MODEL * C_MODEL];  // [3072,1024] (W^T)
__device__ __align__(256) __nv_bfloat16 g_wql[3 * C_MODEL * C_MODEL];
__device__ __align__(256) __nv_bfloat16 g_wph[C_MODEL * C_MODEL];      // [1024,1024] (W^T)
__device__ __align__(256) __nv_bfloat16 g_wpl[C_MODEL * C_MODEL];

// ------------------------- PTX helpers (portable ISA only) -------------------------
__device__ __forceinline__ uint32_t smem_u32(const void* p) {
    uint32_t a;
    asm("{ .reg .u64 t; cvta.to.shared.u64 t, %1; cvt.u32.u64 %0, t; }" : "=r"(a) : "l"(p));
    return a;
}
__device__ __forceinline__ void cpasync16(uint32_t dst, const void* src) {
    asm volatile("cp.async.cg.shared.global [%0], [%1], 16;" :: "r"(dst), "l"(src));
}
#define CP_COMMIT() asm volatile("cp.async.commit_group;" ::: "memory")
#define CP_WAIT(n)  asm volatile("cp.async.wait_group %0;" :: "n"(n) : "memory")

__device__ __forceinline__ void ldsm4(uint32_t& r0, uint32_t& r1, uint32_t& r2, uint32_t& r3,
                                      uint32_t addr) {
    asm volatile("ldmatrix.sync.aligned.m8n8.x4.shared.b16 {%0,%1,%2,%3}, [%4];"
                 : "=r"(r0), "=r"(r1), "=r"(r2), "=r"(r3) : "r"(addr));
}
__device__ __forceinline__ void mma16816(float* c, uint32_t a0, uint32_t a1, uint32_t a2,
                                         uint32_t a3, uint32_t b0, uint32_t b1) {
    asm volatile(
        "mma.sync.aligned.m16n8k16.row.col.f32.bf16.bf16.f32 "
        "{%0,%1,%2,%3}, {%4,%5,%6,%7}, {%8,%9}, {%0,%1,%2,%3};"
        : "+f"(c[0]), "+f"(c[1]), "+f"(c[2]), "+f"(c[3])
        : "r"(a0), "r"(a1), "r"(a2), "r"(a3), "r"(b0), "r"(b1));
}
__device__ __forceinline__ uint32_t packbf2(__nv_bfloat16 a, __nv_bfloat16 b) {
    __nv_bfloat162 t(a, b);
    return *reinterpret_cast<uint32_t*>(&t);
}
// split two floats into packed hi / packed lo bf16x2
__device__ __forceinline__ void split2(float a, float b, uint32_t& hi, uint32_t& lo) {
    __nv_bfloat16 ha = __float2bfloat16(a), hb = __float2bfloat16(b);
    __nv_bfloat16 la = __float2bfloat16(a - __bfloat162float(ha));
    __nv_bfloat16 lb = __float2bfloat16(b - __bfloat162float(hb));
    hi = packbf2(ha, hb);
    lo = packbf2(la, lb);
}

// ------------------------- conversion kernels -------------------------
__global__ void split_kernel(const float* __restrict__ in,
                             __nv_bfloat16* __restrict__ hi,
                             __nv_bfloat16* __restrict__ lo, int n4) {
    int i = blockIdx.x * blockDim.x + threadIdx.x;
    if (i >= n4) return;
    float4 v = ((const float4*)in)[i];
    uint32_t h0, l0, h1, l1;
    split2(v.x, v.y, h0, l0);
    split2(v.z, v.w, h1, l1);
    ((uint32_t*)hi)[2 * i]     = h0;
    ((uint32_t*)hi)[2 * i + 1] = h1;
    ((uint32_t*)lo)[2 * i]     = l0;
    ((uint32_t*)lo)[2 * i + 1] = l1;
}

// W [K, N] fp32 row-major -> Th/Tl [N, K] bf16 (transposed + split)
__global__ void transpose_split(const float* __restrict__ W,
                                __nv_bfloat16* __restrict__ Th,
                                __nv_bfloat16* __restrict__ Tl, int K, int N) {
    __shared__ float t[32][33];
    const int bx = blockIdx.x * 32;   // n offset
    const int by = blockIdx.y * 32;   // k offset
    const int x = threadIdx.x, y = threadIdx.y;
#pragma unroll
    for (int j = 0; j < 32; j += 8)
        t[y + j][x] = W[(size_t)(by + y + j) * N + bx + x];
    __syncthreads();
#pragma unroll
    for (int j = 0; j < 32; j += 8) {
        float v = t[x][y + j];
        __nv_bfloat16 h = __float2bfloat16(v);
        __nv_bfloat16 l = __float2bfloat16(v - __bfloat162float(h));
        size_t o = (size_t)(bx + y + j) * K + by + x;
        Th[o] = h; Tl[o] = l;
    }
}

// ------------------------- mma.sync GEMM -------------------------
// C[8192, NTOT] = A[8192,1024] @ BT[NTOT,1024]^T, bf16 hi/lo x 3 products, fp32 accum.
// CTA tile 128x128, K-stage 32, 256 thr = 8 warps (2m x 4n), warp 64x32, 2 CTAs/SM.
#define GT_M 128
#define GT_N 128
#define GT_K 32
#define G_NSTAGE 32                  // 1024 / 32
#define ROWB 80                      // 64B data + 16B pad
#define OFF_AH 0
#define OFF_AL (128 * ROWB)          // 10240
#define OFF_BH (2 * 128 * ROWB)      // 20480
#define OFF_BL (3 * 128 * ROWB)      // 30720
#define STAGE_B (4 * 128 * ROWB)     // 40960
#define GEMM_SMEM (2 * STAGE_B)      // 81920

template <int NTOT, int EPI>
__global__ void __launch_bounds__(256, 2) mma_gemm(const __nv_bfloat16* __restrict__ Ah_,
                                                   const __nv_bfloat16* __restrict__ Al_,
                                                   const __nv_bfloat16* __restrict__ Bh_,
                                                   const __nv_bfloat16* __restrict__ Bl_,
                                                   float* __restrict__ C) {
    extern __shared__ char sm[];
    const uint32_t sbase = smem_u32(sm);
    const int tid  = threadIdx.x;
    const int lane = tid & 31;
    const int wid  = tid >> 5;
    const int wm   = wid & 1;          // 0..1
    const int wn   = wid >> 1;         // 0..3
    const int row0 = blockIdx.y * GT_M;
    const int col0 = blockIdx.x * GT_N;

    float acc[4][4][4];
#pragma unroll
    for (int i = 0; i < 4; i++)
#pragma unroll
        for (int j = 0; j < 4; j++)
#pragma unroll
            for (int k = 0; k < 4; k++) acc[i][j][k] = 0.f;

    auto load_stage = [&](int kt, int buf) {
        const uint32_t sa = sbase + buf * STAGE_B;
        const int kcol = kt * GT_K;
        // A hi/lo: 128 rows x 64B = 512 chunks per half
#pragma unroll
        for (int p = 0; p < 2; p++) {
            const int i = p * 256 + tid, r = i >> 2, c = i & 3;
            cpasync16(sa + OFF_AH + r * ROWB + c * 16,
                      Ah_ + (size_t)(row0 + r) * 1024 + kcol + c * 8);
            cpasync16(sa + OFF_AL + r * ROWB + c * 16,
                      Al_ + (size_t)(row0 + r) * 1024 + kcol + c * 8);
        }
        // B hi/lo
#pragma unroll
        for (int p = 0; p < 2; p++) {
            const int i = p * 256 + tid, r = i >> 2, c = i & 3;
            cpasync16(sa + OFF_BH + r * ROWB + c * 16,
                      Bh_ + (size_t)(col0 + r) * 1024 + kcol + c * 8);
            cpasync16(sa + OFF_BL + r * ROWB + c * 16,
                      Bl_ + (size_t)(col0 + r) * 1024 + kcol + c * 8);
        }
        CP_COMMIT();
    };

    // ldmatrix base addresses (within stage buffer)
    const uint32_t a_base = OFF_AH + (wm * 64 + (lane & 15)) * ROWB + (lane >> 4) * 16;
    // B x4: covers 2 n8 tiles per ldsm4
    const uint32_t b_base = OFF_BH +
        (wn * 32 + (lane & 7) + ((lane >> 4) << 3)) * ROWB + ((lane >> 3) & 1) * 16;

    load_stage(0, 0);
    load_stage(1, 1);

    for (int kt = 0; kt < G_NSTAGE; kt++) {
        if (kt == G_NSTAGE - 1) { CP_WAIT(0); } else { CP_WAIT(1); }
        __syncthreads();

        const uint32_t sa = sbase + (kt & 1) * STAGE_B;
#pragma unroll
        for (int kk = 0; kk < 2; kk++) {
            const uint32_t koff = kk * 32;
            uint32_t ah[4][4], bh[4][2];
#pragma unroll
            for (int mt = 0; mt < 4; mt++)
                ldsm4(ah[mt][0], ah[mt][1], ah[mt][2], ah[mt][3],
                      sa + a_base + mt * 16 * ROWB + koff);
#pragma unroll
            for (int p = 0; p < 2; p++)
                ldsm4(bh[2 * p][0], bh[2 * p][1], bh[2 * p + 1][0], bh[2 * p + 1][1],
                      sa + b_base + p * 16 * ROWB + koff);
#pragma unroll
            for (int mt = 0; mt < 4; mt++)
#pragma unroll
                for (int nt = 0; nt < 4; nt++)
                    mma16816(acc[mt][nt], ah[mt][0], ah[mt][1], ah[mt][2], ah[mt][3],
                             bh[nt][0], bh[nt][1]);
            {
                uint32_t al[4][4];
#pragma unroll
                for (int mt = 0; mt < 4; mt++)
                    ldsm4(al[mt][0], al[mt][1], al[mt][2], al[mt][3],
                          sa + a_base + (OFF_AL - OFF_AH) + mt * 16 * ROWB + koff);
#pragma unroll
                for (int mt = 0; mt < 4; mt++)
#pragma unroll
                    for (int nt = 0; nt < 4; nt++)
                        mma16816(acc[mt][nt], al[mt][0], al[mt][1], al[mt][2], al[mt][3],
                                 bh[nt][0], bh[nt][1]);
            }
            {
                uint32_t bl[4][2];
#pragma unroll
                for (int p = 0; p < 2; p++)
                    ldsm4(bl[2 * p][0], bl[2 * p][1], bl[2 * p + 1][0], bl[2 * p + 1][1],
                          sa + b_base + (OFF_BL - OFF_BH) + p * 16 * ROWB + koff);
#pragma unroll
                for (int mt = 0; mt < 4; mt++)
#pragma unroll
                    for (int nt = 0; nt < 4; nt++)
                        mma16816(acc[mt][nt], ah[mt][0], ah[mt][1], ah[mt][2], ah[mt][3],
                                 bl[nt][0], bl[nt][1]);
            }
        }
        __syncthreads();
        if (kt + 2 < G_NSTAGE) load_stage(kt + 2, kt & 1);
    }

    // epilogue
    const int rbase = lane >> 2;
    const int cpair = (lane & 3) * 2;
#pragma unroll
    for (int mt = 0; mt < 4; mt++) {
#pragma unroll
        for (int nt = 0; nt < 4; nt++) {
            const float* c = acc[mt][nt];
            const int gcol = col0 + wn * 32 + nt * 8 + cpair;
            const int r1 = row0 + wm * 64 + mt * 16 + rbase;
            if constexpr (EPI == 0) {
                *(float2*)&C[(size_t)r1 * NTOT + gcol]       = make_float2(c[0], c[1]);
                *(float2*)&C[(size_t)(r1 + 8) * NTOT + gcol] = make_float2(c[2], c[3]);
            } else {
                const int part = gcol >> 10;       // 0=Q 1=K 2=V
                const int rem  = gcol & 1023;
                const int h = rem >> 6, d = rem & 63;
#pragma unroll
                for (int hh = 0; hh < 2; hh++) {
                    const int gr = r1 + hh * 8;
                    const int b_ = gr >> 10, t_ = gr & 1023;
                    float v0 = c[hh * 2], v1 = c[hh * 2 + 1];
                    if (part == 0) { v0 *= 0.125f; v1 *= 0.125f; }
                    uint32_t hi, lo;
                    split2(v0, v1, hi, lo);
                    if (part < 2) {
                        __nv_bfloat16* dh = part ? g_kh : g_qh;
                        __nv_bfloat16* dl = part ? g_kl : g_ql;
                        const size_t o = (((size_t)(b_ * N_HEAD + h)) * T_SEQ + t_) * DK + d;
                        *(uint32_t*)&dh[o] = hi;
                        *(uint32_t*)&dl[o] = lo;
                    } else {
                        // V^T: [B,H,dk,T]
                        const size_t o = (((size_t)(b_ * N_HEAD + h)) * DK + d) * T_SEQ + t_;
                        __nv_bfloat162 hv = *reinterpret_cast<__nv_bfloat162*>(&hi);
                        __nv_bfloat162 lv = *reinterpret_cast<__nv_bfloat162*>(&lo);
                        g_vth[o] = hv.x;  g_vth[o + T_SEQ] = hv.y;
                        g_vtl[o] = lv.x;  g_vtl[o + T_SEQ] = lv.y;
                    }
                }
            }
        }
    }
}

// ------------------------- tensor-core flash attention -------------------------
// Grid (16 qt, 128 bh), 128 threads = 4 warps; warp owns 16 q-rows of a 64-row tile.
// S = Q K^T (hi/lo 3-product), online softmax in frags, P hi/lo re-split in regs,
// O += P V via V^T in smem. Writes y as bf16 hi/lo for the proj GEMM.
#define AROWB 144                    // 128B data + 16B pad (conflict-free ldmatrix)
#define ATILE (64 * AROWB)           // 9216
#define AST_KH 0
#define AST_KL ATILE
#define AST_VH (2 * ATILE)
#define AST_VL (3 * ATILE)
#define ASTAGE (4 * ATILE)           // 36864
#define AQ_H (2 * ASTAGE)            // 73728
#define AQ_L (AQ_H + ATILE)
#define ATTN_SMEM (AQ_L + ATILE)     // 92160

__global__ void __launch_bounds__(128) attn_kernel() {
    extern __shared__ char sm[];
    const uint32_t sb = smem_u32(sm);
    const int tid  = threadIdx.x;
    const int lane = tid & 31;
    const int w    = tid >> 5;
    const int qt   = (int)gridDim.x - 1 - (int)blockIdx.x;  // long CTAs first
    const int bh   = blockIdx.y;

    const __nv_bfloat16* Qh = g_qh + (size_t)bh * (T_SEQ * DK);
    const __nv_bfloat16* Ql = g_ql + (size_t)bh * (T_SEQ * DK);
    const __nv_bfloat16* Kh = g_kh + (size_t)bh * (T_SEQ * DK);
    const __nv_bfloat16* Kl = g_kl + (size_t)bh * (T_SEQ * DK);
    const __nv_bfloat16* Vh = g_vth + (size_t)bh * (DK * T_SEQ);
    const __nv_bfloat16* Vl = g_vtl + (size_t)bh * (DK * T_SEQ);

    auto load_kv = [&](int kt, int buf) {
        const uint32_t st = sb + buf * ASTAGE;
        const int t0 = kt * 64;
#pragma unroll
        for (int it = 0; it < 4; it++) {
            const int i = it * 128 + tid;
            const int r = i >> 3, c = i & 7;
            cpasync16(st + AST_KH + r * AROWB + c * 16, Kh + (size_t)(t0 + r) * DK + c * 8);
            cpasync16(st + AST_KL + r * AROWB + c * 16, Kl + (size_t)(t0 + r) * DK + c * 8);
            cpasync16(st + AST_VH + r * AROWB + c * 16, Vh + (size_t)r * T_SEQ + t0 + c * 8);
            cpasync16(st + AST_VL + r * AROWB + c * 16, Vl + (size_t)r * T_SEQ + t0 + c * 8);
        }
        CP_COMMIT();
    };

    // load Q tile hi/lo
#pragma unroll
    for (int it = 0; it < 4; it++) {
        const int i = it * 128 + tid;
        const int r = i >> 3, c = i & 7;
        cpasync16(sb + AQ_H + r * AROWB + c * 16, Qh + (size_t)(qt * 64 + r) * DK + c * 8);
        cpasync16(sb + AQ_L + r * AROWB + c * 16, Ql + (size_t)(qt * 64 + r) * DK + c * 8);
    }
    CP_COMMIT();
    load_kv(0, 0);

    CP_WAIT(1);          // Q ready
    __syncthreads();

    // Q fragments (persist in regs)
    uint32_t qh[4][4], ql[4][4];
    {
        const uint32_t qa = sb + AQ_H + (w * 16 + (lane & 15)) * AROWB + (lane >> 4) * 16;
#pragma unroll
        for (int ks = 0; ks < 4; ks++) {
            ldsm4(qh[ks][0], qh[ks][1], qh[ks][2], qh[ks][3], qa + ks * 32);
            ldsm4(ql[ks][0], ql[ks][1], ql[ks][2], ql[ks][3], qa + (AQ_L - AQ_H) + ks * 32);
        }
    }

    float O[8][4];
#pragma unroll
    for (int i = 0; i < 8; i++)
#pragma unroll
        for (int j = 0; j < 4; j++) O[i][j] = 0.f;
    float m0 = -3.0e38f, m1 = -3.0e38f, l0 = 0.f, l1 = 0.f;

    // B-frag ldmatrix address pattern (2 n8 tiles per ldsm4)
    const uint32_t bpat = ((lane & 7) + ((lane >> 4) << 3)) * AROWB + ((lane >> 3) & 1) * 16;

    for (int kt = 0; kt <= qt; kt++) {
        if (kt < qt) { load_kv(kt + 1, (kt + 1) & 1); CP_WAIT(1); } else { CP_WAIT(0); }
        __syncthreads();
        const uint32_t st = sb + (kt & 1) * ASTAGE;

        // ---- S = Q K^T ----
        float S[8][4];
#pragma unroll
        for (int i = 0; i < 8; i++)
#pragma unroll
            for (int j = 0; j < 4; j++) S[i][j] = 0.f;

#pragma unroll
        for (int ks = 0; ks < 4; ks++) {
            uint32_t kh[8][2], kl[8][2];
#pragma unroll
            for (int p = 0; p < 4; p++) {
                ldsm4(kh[2 * p][0], kh[2 * p][1], kh[2 * p + 1][0], kh[2 * p + 1][1],
                      st + AST_KH + p * 16 * AROWB + bpat + ks * 32);
                ldsm4(kl[2 * p][0], kl[2 * p][1], kl[2 * p + 1][0], kl[2 * p + 1][1],
                      st + AST_KL + p * 16 * AROWB + bpat + ks * 32);
            }
#pragma unroll
            for (int nt = 0; nt < 8; nt++) {
                mma16816(S[nt], qh[ks][0], qh[ks][1], qh[ks][2], qh[ks][3], kh[nt][0], kh[nt][1]);
                mma16816(S[nt], ql[ks][0], ql[ks][1], ql[ks][2], ql[ks][3], kh[nt][0], kh[nt][1]);
                mma16816(S[nt], qh[ks][0], qh[ks][1], qh[ks][2], qh[ks][3], kl[nt][0], kl[nt][1]);
            }
        }

        // ---- causal mask on diagonal tile ----
        if (kt == qt) {
            const int grow = qt * 64 + w * 16 + (lane >> 2);
#pragma unroll
            for (int nt = 0; nt < 8; nt++) {
                const int col = qt * 64 + nt * 8 + (lane & 3) * 2;
                if (col     > grow)     S[nt][0] = -3.0e38f;
                if (col + 1 > grow)     S[nt][1] = -3.0e38f;
                if (col     > grow + 8) S[nt][2] = -3.0e38f;
                if (col + 1 > grow + 8) S[nt][3] = -3.0e38f;
            }
        }

        // ---- online softmax ----
        float mx0 = -3.0e38f, mx1 = -3.0e38f;
#pragma unroll
        for (int nt = 0; nt < 8; nt++) {
            mx0 = fmaxf(mx0, fmaxf(S[nt][0], S[nt][1]));
            mx1 = fmaxf(mx1, fmaxf(S[nt][2], S[nt][3]));
        }
        mx0 = fmaxf(mx0, __shfl_xor_sync(0xffffffffu, mx0, 1));
        mx0 = fmaxf(mx0, __shfl_xor_sync(0xffffffffu, mx0, 2));
        mx1 = fmaxf(mx1, __shfl_xor_sync(0xffffffffu, mx1, 1));
        mx1 = fmaxf(mx1, __shfl_xor_sync(0xffffffffu, mx1, 2));
        const float mn0 = fmaxf(m0, mx0);
        const float mn1 = fmaxf(m1, mx1);
        const float sc0 = __expf(m0 - mn0);
        const float sc1 = __expf(m1 - mn1);
        float sum0 = 0.f, sum1 = 0.f;
#pragma unroll
        for (int nt = 0; nt < 8; nt++) {
            S[nt][0] = __expf(S[nt][0] - mn0); sum0 += S[nt][0];
            S[nt][1] = __expf(S[nt][1] - mn0); sum0 += S[nt][1];
            S[nt][2] = __expf(S[nt][2] - mn1); sum1 += S[nt][2];
            S[nt][3] = __expf(S[nt][3] - mn1); sum1 += S[nt][3];
        }
        sum0 += __shfl_xor_sync(0xffffffffu, sum0, 1);
        sum0 += __shfl_xor_sync(0xffffffffu, sum0, 2);
        sum1 += __shfl_xor_sync(0xffffffffu, sum1, 1);
        sum1 += __shfl_xor_sync(0xffffffffu, sum1, 2);
        l0 = l0 * sc0 + sum0;
        l1 = l1 * sc1 + sum1;
        m0 = mn0; m1 = mn1;
#pragma unroll
        for (int nt = 0; nt < 8; nt++) {
            O[nt][0] *= sc0; O[nt][1] *= sc0;
            O[nt][2] *= sc1; O[nt][3] *= sc1;
        }

        // ---- O += P V  (P from S frags, hi/lo) ----
#pragma unroll
        for (int ks = 0; ks < 4; ks++) {
            uint32_t ah[4], al[4];
            split2(S[2 * ks][0],     S[2 * ks][1],     ah[0], al[0]);
            split2(S[2 * ks][2],     S[2 * ks][3],     ah[1], al[1]);
            split2(S[2 * ks + 1][0], S[2 * ks + 1][1], ah[2], al[2]);
            split2(S[2 * ks + 1][2], S[2 * ks + 1][3], ah[3], al[3]);
            uint32_t vh[8][2], vl[8][2];
#pragma unroll
            for (int p = 0; p < 4; p++) {
                ldsm4(vh[2 * p][0], vh[2 * p][1], vh[2 * p + 1][0], vh[2 * p + 1][1],
                      st + AST_VH + p * 16 * AROWB + bpat + ks * 32);
                ldsm4(vl[2 * p][0], vl[2 * p][1], vl[2 * p + 1][0], vl[2 * p + 1][1],
                      st + AST_VL + p * 16 * AROWB + bpat + ks * 32);
            }
#pragma unroll
            for (int nt = 0; nt < 8; nt++) {
                mma16816(O[nt], ah[0], ah[1], ah[2], ah[3], vh[nt][0], vh[nt][1]);
                mma16816(O[nt], al[0], al[1], al[2], al[3], vh[nt][0], vh[nt][1]);
                mma16816(O[nt], ah[0], ah[1], ah[2], ah[3], vl[nt][0], vl[nt][1]);
            }
        }
        __syncthreads();
    }

    // ---- epilogue: y = O / l, split hi/lo ----
    const float inv0 = 1.0f / l0;
    const float inv1 = 1.0f / l1;
    const int b_ = bh >> 4, h_ = bh & 15;
    const int t0 = qt * 64 + w * 16 + (lane >> 2);
#pragma unroll
    for (int nt = 0; nt < 8; nt++) {
        const int d = nt * 8 + (lane & 3) * 2;
        uint32_t hi, lo;
        split2(O[nt][0] * inv0, O[nt][1] * inv0, hi, lo);
        size_t o = ((size_t)(b_ * T_SEQ + t0)) * C_MODEL + h_ * DK + d;
        *(uint32_t*)&g_yh[o] = hi;
        *(uint32_t*)&g_yl[o] = lo;
        split2(O[nt][2] * inv1, O[nt][3] * inv1, hi, lo);
        o = ((size_t)(b_ * T_SEQ + t0 + 8)) * C_MODEL + h_ * DK + d;
        *(uint32_t*)&g_yh[o] = hi;
        *(uint32_t*)&g_yl[o] = lo;
    }
}

// ---------------------------------------------------------------------------

extern "C" void kernel_launch(void* const* d_in, const int* in_sizes, int n_in,
                              void* d_out, int out_size) {
    const float* x     = (const float*)d_in[0];   // [8,1024,1024]
    const float* wqkv  = (const float*)d_in[1];   // [1024,3072]
    const float* wproj = (const float*)d_in[2];   // [1024,1024]
    float* out = (float*)d_out;                   // [8,1024,1024]

    cudaFuncSetAttribute(attn_kernel,
                         cudaFuncAttributeMaxDynamicSharedMemorySize, ATTN_SMEM);
    cudaFuncSetAttribute(mma_gemm<3072, 1>,
                         cudaFuncAttributeMaxDynamicSharedMemorySize, GEMM_SMEM);
    cudaFuncSetAttribute(mma_gemm<1024, 0>,
                         cudaFuncAttributeMaxDynamicSharedMemorySize, GEMM_SMEM);

    __nv_bfloat16 *xh, *xl, *yh, *yl, *wqh, *wql, *wph, *wpl;
    cudaGetSymbolAddress((void**)&xh,  g_xh);
    cudaGetSymbolAddress((void**)&xl,  g_xl);
    cudaGetSymbolAddress((void**)&yh,  g_yh);
    cudaGetSymbolAddress((void**)&yl,  g_yl);
    cudaGetSymbolAddress((void**)&wqh, g_wqh);
    cudaGetSymbolAddress((void**)&wql, g_wql);
    cudaGetSymbolAddress((void**)&wph, g_wph);
    cudaGetSymbolAddress((void**)&wpl, g_wpl);

    // 1) fp32 -> bf16 hi/lo conversions
    split_kernel<<<(M_ROWS * C_MODEL / 4 + 255) / 256, 256>>>(x, xh, xl, M_ROWS * C_MODEL / 4);
    transpose_split<<<dim3(3072 / 32, 1024 / 32), dim3(32, 8)>>>(wqkv, wqh, wql, 1024, 3072);
    transpose_split<<<dim3(1024 / 32, 1024 / 32), dim3(32, 8)>>>(wproj, wph, wpl, 1024, 1024);

    // 2) QKV projection -> bf16 hi/lo Q(scaled)/K/V^T
    mma_gemm<3072, 1><<<dim3(3072 / GT_N, M_ROWS / GT_M), 256, GEMM_SMEM>>>(
        xh, xl, wqh, wql, nullptr);

    // 3) tensor-core causal attention -> g_yh/g_yl
    attn_kernel<<<dim3(T_SEQ / 64, N_BATCH * N_HEAD), 128, ATTN_SMEM>>>();

    // 4) output projection
    mma_gemm<1024, 0><<<dim3(1024 / GT_N, M_ROWS / GT_M), 256, GEMM_SMEM>>>(
        yh, yl, wph, wpl, out);
}

// round 5
// speedup vs baseline: 3.8528x; 1.4834x over previous
#include <cuda_runtime.h>
#include <cuda_fp16.h>
#include <cstdint>
#include <math.h>

// Problem constants
#define C_MODEL 1024
#define N_HEAD  16
#define DK      64
#define T_SEQ   1024
#define N_BATCH 8
#define M_ROWS  (N_BATCH * T_SEQ)   // 8192
#define QKD     (N_BATCH * N_HEAD * T_SEQ * DK)   // 8388608

// ------------------------- scratch (device globals) -------------------------
__device__ __align__(256) __half g_xh[M_ROWS * C_MODEL];
__device__ __align__(256) __half g_xl[M_ROWS * C_MODEL];
__device__ __align__(256) __half g_qh[QKD];   // [B,H,T,dk], pre-scaled by 0.125
__device__ __align__(256) __half g_ql[QKD];
__device__ __align__(256) __half g_kh[QKD];   // [B,H,T,dk]  (hi only)
__device__ __align__(256) __half g_vth[QKD];  // [B,H,dk,T]  (V transposed, hi only)
__device__ __align__(256) __half g_yh[M_ROWS * C_MODEL];   // attn out hi
__device__ __align__(256) __half g_yl[M_ROWS * C_MODEL];   // attn out lo
__device__ __align__(256) __half g_wqh[3 * C_MODEL * C_MODEL];  // [3072,1024] (W^T, hi)
__device__ __align__(256) __half g_wph[C_MODEL * C_MODEL];      // [1024,1024] (W^T, hi)

// ------------------------- PTX helpers -------------------------
__device__ __forceinline__ uint32_t smem_u32(const void* p) {
    uint32_t a;
    asm("{ .reg .u64 t; cvta.to.shared.u64 t, %1; cvt.u32.u64 %0, t; }" : "=r"(a) : "l"(p));
    return a;
}
__device__ __forceinline__ void cpasync16(uint32_t dst, const void* src) {
    asm volatile("cp.async.cg.shared.global [%0], [%1], 16;" :: "r"(dst), "l"(src));
}
#define CP_COMMIT() asm volatile("cp.async.commit_group;" ::: "memory")
#define CP_WAIT(n)  asm volatile("cp.async.wait_group %0;" :: "n"(n) : "memory")

__device__ __forceinline__ void ldsm4(uint32_t& r0, uint32_t& r1, uint32_t& r2, uint32_t& r3,
                                      uint32_t addr) {
    asm volatile("ldmatrix.sync.aligned.m8n8.x4.shared.b16 {%0,%1,%2,%3}, [%4];"
                 : "=r"(r0), "=r"(r1), "=r"(r2), "=r"(r3) : "r"(addr));
}
__device__ __forceinline__ void mma16816(float* c, uint32_t a0, uint32_t a1, uint32_t a2,
                                         uint32_t a3, uint32_t b0, uint32_t b1) {
    asm volatile(
        "mma.sync.aligned.m16n8k16.row.col.f32.f16.f16.f32 "
        "{%0,%1,%2,%3}, {%4,%5,%6,%7}, {%8,%9}, {%0,%1,%2,%3};"
        : "+f"(c[0]), "+f"(c[1]), "+f"(c[2]), "+f"(c[3])
        : "r"(a0), "r"(a1), "r"(a2), "r"(a3), "r"(b0), "r"(b1));
}
__device__ __forceinline__ uint32_t packh2(__half a, __half b) {
    __half2 t(a, b);
    return *reinterpret_cast<uint32_t*>(&t);
}
// split two floats into packed hi / packed lo half2
__device__ __forceinline__ void split2h(float a, float b, uint32_t& hi, uint32_t& lo) {
    __half ha = __float2half_rn(a), hb = __float2half_rn(b);
    __half la = __float2half_rn(a - __half2float(ha));
    __half lb = __float2half_rn(b - __half2float(hb));
    hi = packh2(ha, hb);
    lo = packh2(la, lb);
}
__device__ __forceinline__ uint32_t pack2h(float a, float b) {
    __half2 t = __floats2half2_rn(a, b);
    return *reinterpret_cast<uint32_t*>(&t);
}

// ------------------------- conversion kernels -------------------------
__global__ void split_kernel(const float* __restrict__ in,
                             __half* __restrict__ hi,
                             __half* __restrict__ lo, int n4) {
    int i = blockIdx.x * blockDim.x + threadIdx.x;
    if (i >= n4) return;
    float4 v = ((const float4*)in)[i];
    uint32_t h0, l0, h1, l1;
    split2h(v.x, v.y, h0, l0);
    split2h(v.z, v.w, h1, l1);
    ((uint32_t*)hi)[2 * i]     = h0;
    ((uint32_t*)hi)[2 * i + 1] = h1;
    ((uint32_t*)lo)[2 * i]     = l0;
    ((uint32_t*)lo)[2 * i + 1] = l1;
}

// W [K, N] fp32 row-major -> Th [N, K] fp16 (transposed + rounded, hi only)
__global__ void transpose_round(const float* __restrict__ W,
                                __half* __restrict__ Th, int K, int N) {
    __shared__ float t[32][33];
    const int bx = blockIdx.x * 32;   // n offset
    const int by = blockIdx.y * 32;   // k offset
    const int x = threadIdx.x, y = threadIdx.y;
#pragma unroll
    for (int j = 0; j < 32; j += 8)
        t[y + j][x] = W[(size_t)(by + y + j) * N + bx + x];
    __syncthreads();
#pragma unroll
    for (int j = 0; j < 32; j += 8)
        Th[(size_t)(bx + y + j) * K + by + x] = __float2half_rn(t[x][y + j]);
}

// ------------------------- mma.sync GEMM (fp16, 2-product) -------------------------
// C[8192, NTOT] = (Ah+Al)[8192,1024] @ Bh[NTOT,1024]^T, fp32 accum.
// CTA tile 128x128, K-stage 32, 3-stage cp.async ring, one sync per stage.
// 256 thr = 8 warps (2m x 4n), warp 64x32, 2 CTAs/SM.
#define GT_M 128
#define GT_N 128
#define GT_K 32
#define G_NSTAGE 32                  // 1024 / 32
#define ROWB 80                      // 64B data + 16B pad
#define OFF_AH 0
#define OFF_AL (128 * ROWB)          // 10240
#define OFF_BH (2 * 128 * ROWB)      // 20480
#define STAGE_B (3 * 128 * ROWB)     // 30720
#define GEMM_SMEM (3 * STAGE_B)      // 92160

template <int NTOT, int EPI>
__global__ void __launch_bounds__(256, 2) mma_gemm(const __half* __restrict__ Ah_,
                                                   const __half* __restrict__ Al_,
                                                   const __half* __restrict__ Bh_,
                                                   float* __restrict__ C) {
    extern __shared__ char sm[];
    const uint32_t sbase = smem_u32(sm);
    const int tid  = threadIdx.x;
    const int lane = tid & 31;
    const int wid  = tid >> 5;
    const int wm   = wid & 1;          // 0..1
    const int wn   = wid >> 1;         // 0..3
    const int row0 = blockIdx.y * GT_M;
    const int col0 = blockIdx.x * GT_N;

    float acc[4][4][4];
#pragma unroll
    for (int i = 0; i < 4; i++)
#pragma unroll
        for (int j = 0; j < 4; j++)
#pragma unroll
            for (int k = 0; k < 4; k++) acc[i][j][k] = 0.f;

    auto load_stage = [&](int kt, int buf) {
        const uint32_t sa = sbase + buf * STAGE_B;
        const int kcol = kt * GT_K;
        // each tile: 128 rows x 64B = 512 x 16B chunks / 256 thr = 2 per thread
#pragma unroll
        for (int p = 0; p < 2; p++) {
            const int i = p * 256 + tid, r = i >> 2, c = i & 3;
            cpasync16(sa + OFF_AH + r * ROWB + c * 16,
                      Ah_ + (size_t)(row0 + r) * 1024 + kcol + c * 8);
            cpasync16(sa + OFF_AL + r * ROWB + c * 16,
                      Al_ + (size_t)(row0 + r) * 1024 + kcol + c * 8);
            cpasync16(sa + OFF_BH + r * ROWB + c * 16,
                      Bh_ + (size_t)(col0 + r) * 1024 + kcol + c * 8);
        }
        CP_COMMIT();
    };

    // ldmatrix base addresses (within a stage buffer)
    const uint32_t a_base = OFF_AH + (wm * 64 + (lane & 15)) * ROWB + (lane >> 4) * 16;
    const uint32_t b_base = OFF_BH +
        (wn * 32 + (lane & 7) + ((lane >> 4) << 3)) * ROWB + ((lane >> 3) & 1) * 16;

    load_stage(0, 0);
    load_stage(1, 1);

    for (int kt = 0; kt < G_NSTAGE; kt++) {
        if (kt == G_NSTAGE - 1) { CP_WAIT(0); } else { CP_WAIT(1); }
        __syncthreads();
        // issue next-next stage load immediately (buf (kt+2)%3 was finished at kt-1)
        if (kt + 2 < G_NSTAGE) load_stage(kt + 2, (kt + 2) % 3);

        const uint32_t sa = sbase + (kt % 3) * STAGE_B;
#pragma unroll
        for (int kk = 0; kk < 2; kk++) {
            const uint32_t koff = kk * 32;
            uint32_t ah[4][4], bh[4][2];
#pragma unroll
            for (int mt = 0; mt < 4; mt++)
                ldsm4(ah[mt][0], ah[mt][1], ah[mt][2], ah[mt][3],
                      sa + a_base + mt * 16 * ROWB + koff);
#pragma unroll
            for (int p = 0; p < 2; p++)
                ldsm4(bh[2 * p][0], bh[2 * p][1], bh[2 * p + 1][0], bh[2 * p + 1][1],
                      sa + b_base + p * 16 * ROWB + koff);
#pragma unroll
            for (int mt = 0; mt < 4; mt++)
#pragma unroll
                for (int nt = 0; nt < 4; nt++)
                    mma16816(acc[mt][nt], ah[mt][0], ah[mt][1], ah[mt][2], ah[mt][3],
                             bh[nt][0], bh[nt][1]);
            {
                uint32_t al[4][4];
#pragma unroll
                for (int mt = 0; mt < 4; mt++)
                    ldsm4(al[mt][0], al[mt][1], al[mt][2], al[mt][3],
                          sa + a_base + (OFF_AL - OFF_AH) + mt * 16 * ROWB + koff);
#pragma unroll
                for (int mt = 0; mt < 4; mt++)
#pragma unroll
                    for (int nt = 0; nt < 4; nt++)
                        mma16816(acc[mt][nt], al[mt][0], al[mt][1], al[mt][2], al[mt][3],
                                 bh[nt][0], bh[nt][1]);
            }
        }
    }

    // epilogue
    const int rbase = lane >> 2;
    const int cpair = (lane & 3) * 2;
#pragma unroll
    for (int mt = 0; mt < 4; mt++) {
#pragma unroll
        for (int nt = 0; nt < 4; nt++) {
            const float* c = acc[mt][nt];
            const int gcol = col0 + wn * 32 + nt * 8 + cpair;
            const int r1 = row0 + wm * 64 + mt * 16 + rbase;
            if constexpr (EPI == 0) {
                *(float2*)&C[(size_t)r1 * NTOT + gcol]       = make_float2(c[0], c[1]);
                *(float2*)&C[(size_t)(r1 + 8) * NTOT + gcol] = make_float2(c[2], c[3]);
            } else {
                const int part = gcol >> 10;       // 0=Q 1=K 2=V
                const int rem  = gcol & 1023;
                const int h = rem >> 6, d = rem & 63;
#pragma unroll
                for (int hh = 0; hh < 2; hh++) {
                    const int gr = r1 + hh * 8;
                    const int b_ = gr >> 10, t_ = gr & 1023;
                    const float v0 = c[hh * 2], v1 = c[hh * 2 + 1];
                    if (part == 0) {
                        uint32_t hi, lo;
                        split2h(v0 * 0.125f, v1 * 0.125f, hi, lo);
                        const size_t o = (((size_t)(b_ * N_HEAD + h)) * T_SEQ + t_) * DK + d;
                        *(uint32_t*)&g_qh[o] = hi;
                        *(uint32_t*)&g_ql[o] = lo;
                    } else if (part == 1) {
                        const size_t o = (((size_t)(b_ * N_HEAD + h)) * T_SEQ + t_) * DK + d;
                        *(uint32_t*)&g_kh[o] = pack2h(v0, v1);
                    } else {
                        // V^T: [B,H,dk,T]
                        const size_t o = (((size_t)(b_ * N_HEAD + h)) * DK + d) * T_SEQ + t_;
                        g_vth[o]         = __float2half_rn(v0);
                        g_vth[o + T_SEQ] = __float2half_rn(v1);
                    }
                }
            }
        }
    }
}

// ------------------------- tensor-core flash attention (fp16) -------------------------
// Grid (16 qt, 128 bh), 128 threads = 4 warps; warp owns 16 q-rows of a 64-row tile.
// S = (Qh+Ql) Kh^T (2 products), online softmax in frags, O += P V (P fp16, 1 product).
#define AROWB 144                    // 128B data + 16B pad
#define ATILE (64 * AROWB)           // 9216
#define AST_KH 0
#define AST_VH ATILE
#define ASTAGE (2 * ATILE)           // 18432
#define AQ_H (2 * ASTAGE)            // 36864
#define AQ_L (AQ_H + ATILE)
#define ATTN_SMEM (AQ_L + ATILE)     // 55296

__global__ void __launch_bounds__(128) attn_kernel() {
    extern __shared__ char sm[];
    const uint32_t sb = smem_u32(sm);
    const int tid  = threadIdx.x;
    const int lane = tid & 31;
    const int w    = tid >> 5;
    const int qt   = (int)gridDim.x - 1 - (int)blockIdx.x;  // long CTAs first
    const int bh   = blockIdx.y;

    const __half* Qh = g_qh + (size_t)bh * (T_SEQ * DK);
    const __half* Ql = g_ql + (size_t)bh * (T_SEQ * DK);
    const __half* Kh = g_kh + (size_t)bh * (T_SEQ * DK);
    const __half* Vh = g_vth + (size_t)bh * (DK * T_SEQ);

    auto load_kv = [&](int kt, int buf) {
        const uint32_t st = sb + buf * ASTAGE;
        const int t0 = kt * 64;
#pragma unroll
        for (int it = 0; it < 4; it++) {
            const int i = it * 128 + tid;
            const int r = i >> 3, c = i & 7;
            cpasync16(st + AST_KH + r * AROWB + c * 16, Kh + (size_t)(t0 + r) * DK + c * 8);
            cpasync16(st + AST_VH + r * AROWB + c * 16, Vh + (size_t)r * T_SEQ + t0 + c * 8);
        }
        CP_COMMIT();
    };

    // load Q tile hi/lo
#pragma unroll
    for (int it = 0; it < 4; it++) {
        const int i = it * 128 + tid;
        const int r = i >> 3, c = i & 7;
        cpasync16(sb + AQ_H + r * AROWB + c * 16, Qh + (size_t)(qt * 64 + r) * DK + c * 8);
        cpasync16(sb + AQ_L + r * AROWB + c * 16, Ql + (size_t)(qt * 64 + r) * DK + c * 8);
    }
    CP_COMMIT();
    load_kv(0, 0);

    CP_WAIT(1);          // Q ready
    __syncthreads();

    // Q fragments (persist in regs)
    uint32_t qh[4][4], ql[4][4];
    {
        const uint32_t qa = sb + AQ_H + (w * 16 + (lane & 15)) * AROWB + (lane >> 4) * 16;
#pragma unroll
        for (int ks = 0; ks < 4; ks++) {
            ldsm4(qh[ks][0], qh[ks][1], qh[ks][2], qh[ks][3], qa + ks * 32);
            ldsm4(ql[ks][0], ql[ks][1], ql[ks][2], ql[ks][3], qa + (AQ_L - AQ_H) + ks * 32);
        }
    }

    float O[8][4];
#pragma unroll
    for (int i = 0; i < 8; i++)
#pragma unroll
        for (int j = 0; j < 4; j++) O[i][j] = 0.f;
    float m0 = -3.0e38f, m1 = -3.0e38f, l0 = 0.f, l1 = 0.f;

    const uint32_t bpat = ((lane & 7) + ((lane >> 4) << 3)) * AROWB + ((lane >> 3) & 1) * 16;

    for (int kt = 0; kt <= qt; kt++) {
        if (kt < qt) { load_kv(kt + 1, (kt + 1) & 1); CP_WAIT(1); } else { CP_WAIT(0); }
        __syncthreads();
        const uint32_t st = sb + (kt & 1) * ASTAGE;

        // ---- S = (Qh+Ql) Kh^T ----
        float S[8][4];
#pragma unroll
        for (int i = 0; i < 8; i++)
#pragma unroll
            for (int j = 0; j < 4; j++) S[i][j] = 0.f;

#pragma unroll
        for (int ks = 0; ks < 4; ks++) {
            uint32_t kh[8][2];
#pragma unroll
            for (int p = 0; p < 4; p++)
                ldsm4(kh[2 * p][0], kh[2 * p][1], kh[2 * p + 1][0], kh[2 * p + 1][1],
                      st + AST_KH + p * 16 * AROWB + bpat + ks * 32);
#pragma unroll
            for (int nt = 0; nt < 8; nt++) {
                mma16816(S[nt], qh[ks][0], qh[ks][1], qh[ks][2], qh[ks][3], kh[nt][0], kh[nt][1]);
                mma16816(S[nt], ql[ks][0], ql[ks][1], ql[ks][2], ql[ks][3], kh[nt][0], kh[nt][1]);
            }
        }

        // ---- causal mask on diagonal tile ----
        if (kt == qt) {
            const int grow = qt * 64 + w * 16 + (lane >> 2);
#pragma unroll
            for (int nt = 0; nt < 8; nt++) {
                const int col = qt * 64 + nt * 8 + (lane & 3) * 2;
                if (col     > grow)     S[nt][0] = -3.0e38f;
                if (col + 1 > grow)     S[nt][1] = -3.0e38f;
                if (col     > grow + 8) S[nt][2] = -3.0e38f;
                if (col + 1 > grow + 8) S[nt][3] = -3.0e38f;
            }
        }

        // ---- online softmax ----
        float mx0 = -3.0e38f, mx1 = -3.0e38f;
#pragma unroll
        for (int nt = 0; nt < 8; nt++) {
            mx0 = fmaxf(mx0, fmaxf(S[nt][0], S[nt][1]));
            mx1 = fmaxf(mx1, fmaxf(S[nt][2], S[nt][3]));
        }
        mx0 = fmaxf(mx0, __shfl_xor_sync(0xffffffffu, mx0, 1));
        mx0 = fmaxf(mx0, __shfl_xor_sync(0xffffffffu, mx0, 2));
        mx1 = fmaxf(mx1, __shfl_xor_sync(0xffffffffu, mx1, 1));
        mx1 = fmaxf(mx1, __shfl_xor_sync(0xffffffffu, mx1, 2));
        const float mn0 = fmaxf(m0, mx0);
        const float mn1 = fmaxf(m1, mx1);
        const float sc0 = __expf(m0 - mn0);
        const float sc1 = __expf(m1 - mn1);
        float sum0 = 0.f, sum1 = 0.f;
#pragma unroll
        for (int nt = 0; nt < 8; nt++) {
            S[nt][0] = __expf(S[nt][0] - mn0); sum0 += S[nt][0];
            S[nt][1] = __expf(S[nt][1] - mn0); sum0 += S[nt][1];
            S[nt][2] = __expf(S[nt][2] - mn1); sum1 += S[nt][2];
            S[nt][3] = __expf(S[nt][3] - mn1); sum1 += S[nt][3];
        }
        sum0 += __shfl_xor_sync(0xffffffffu, sum0, 1);
        sum0 += __shfl_xor_sync(0xffffffffu, sum0, 2);
        sum1 += __shfl_xor_sync(0xffffffffu, sum1, 1);
        sum1 += __shfl_xor_sync(0xffffffffu, sum1, 2);
        l0 = l0 * sc0 + sum0;
        l1 = l1 * sc1 + sum1;
        m0 = mn0; m1 = mn1;
#pragma unroll
        for (int nt = 0; nt < 8; nt++) {
            O[nt][0] *= sc0; O[nt][1] *= sc0;
            O[nt][2] *= sc1; O[nt][3] *= sc1;
        }

        // ---- O += P V  (P packed fp16, single product) ----
#pragma unroll
        for (int ks = 0; ks < 4; ks++) {
            uint32_t pa[4];
            pa[0] = pack2h(S[2 * ks][0],     S[2 * ks][1]);
            pa[1] = pack2h(S[2 * ks][2],     S[2 * ks][3]);
            pa[2] = pack2h(S[2 * ks + 1][0], S[2 * ks + 1][1]);
            pa[3] = pack2h(S[2 * ks + 1][2], S[2 * ks + 1][3]);
            uint32_t vh[8][2];
#pragma unroll
            for (int p = 0; p < 4; p++)
                ldsm4(vh[2 * p][0], vh[2 * p][1], vh[2 * p + 1][0], vh[2 * p + 1][1],
                      st + AST_VH + p * 16 * AROWB + bpat + ks * 32);
#pragma unroll
            for (int nt = 0; nt < 8; nt++)
                mma16816(O[nt], pa[0], pa[1], pa[2], pa[3], vh[nt][0], vh[nt][1]);
        }
        __syncthreads();
    }

    // ---- epilogue: y = O / l, split hi/lo for the proj GEMM ----
    const float inv0 = 1.0f / l0;
    const float inv1 = 1.0f / l1;
    const int b_ = bh >> 4, h_ = bh & 15;
    const int t0 = qt * 64 + w * 16 + (lane >> 2);
#pragma unroll
    for (int nt = 0; nt < 8; nt++) {
        const int d = nt * 8 + (lane & 3) * 2;
        uint32_t hi, lo;
        split2h(O[nt][0] * inv0, O[nt][1] * inv0, hi, lo);
        size_t o = ((size_t)(b_ * T_SEQ + t0)) * C_MODEL + h_ * DK + d;
        *(uint32_t*)&g_yh[o] = hi;
        *(uint32_t*)&g_yl[o] = lo;
        split2h(O[nt][2] * inv1, O[nt][3] * inv1, hi, lo);
        o = ((size_t)(b_ * T_SEQ + t0 + 8)) * C_MODEL + h_ * DK + d;
        *(uint32_t*)&g_yh[o] = hi;
        *(uint32_t*)&g_yl[o] = lo;
    }
}

// ---------------------------------------------------------------------------

extern "C" void kernel_launch(void* const* d_in, const int* in_sizes, int n_in,
                              void* d_out, int out_size) {
    const float* x     = (const float*)d_in[0];   // [8,1024,1024]
    const float* wqkv  = (const float*)d_in[1];   // [1024,3072]
    const float* wproj = (const float*)d_in[2];   // [1024,1024]
    float* out = (float*)d_out;                   // [8,1024,1024]

    cudaFuncSetAttribute(attn_kernel,
                         cudaFuncAttributeMaxDynamicSharedMemorySize, ATTN_SMEM);
    cudaFuncSetAttribute(mma_gemm<3072, 1>,
                         cudaFuncAttributeMaxDynamicSharedMemorySize, GEMM_SMEM);
    cudaFuncSetAttribute(mma_gemm<1024, 0>,
                         cudaFuncAttributeMaxDynamicSharedMemorySize, GEMM_SMEM);

    __half *xh, *xl, *yh, *yl, *wqh, *wph;
    cudaGetSymbolAddress((void**)&xh,  g_xh);
    cudaGetSymbolAddress((void**)&xl,  g_xl);
    cudaGetSymbolAddress((void**)&yh,  g_yh);
    cudaGetSymbolAddress((void**)&yl,  g_yl);
    cudaGetSymbolAddress((void**)&wqh, g_wqh);
    cudaGetSymbolAddress((void**)&wph, g_wph);

    // 1) fp32 -> fp16 conversions (x split hi/lo; weights transposed + rounded)
    split_kernel<<<(M_ROWS * C_MODEL / 4 + 255) / 256, 256>>>(x, xh, xl, M_ROWS * C_MODEL / 4);
    transpose_round<<<dim3(3072 / 32, 1024 / 32), dim3(32, 8)>>>(wqkv, wqh, 1024, 3072);
    transpose_round<<<dim3(1024 / 32, 1024 / 32), dim3(32, 8)>>>(wproj, wph, 1024, 1024);

    // 2) QKV projection -> fp16 Q(hi/lo, scaled) / K(hi) / V^T(hi)
    mma_gemm<3072, 1><<<dim3(3072 / GT_N, M_ROWS / GT_M), 256, GEMM_SMEM>>>(
        xh, xl, wqh, nullptr);

    // 3) tensor-core causal attention -> g_yh/g_yl
    attn_kernel<<<dim3(T_SEQ / 64, N_BATCH * N_HEAD), 128, ATTN_SMEM>>>();

    // 4) output projection
    mma_gemm<1024, 0><<<dim3(1024 / GT_N, M_ROWS / GT_M), 256, GEMM_SMEM>>>(
        yh, yl, wph, out);
}

// round 6
// speedup vs baseline: 3.9352x; 1.0214x over previous
#include <cuda_runtime.h>
#include <cuda_fp16.h>
#include <cstdint>
#include <math.h>

// Problem constants
#define C_MODEL 1024
#define N_HEAD  16
#define DK      64
#define T_SEQ   1024
#define N_BATCH 8
#define M_ROWS  (N_BATCH * T_SEQ)   // 8192
#define QKD     (N_BATCH * N_HEAD * T_SEQ * DK)   // 8388608

// ------------------------- scratch (device globals) -------------------------
__device__ __align__(256) __half g_xh[M_ROWS * C_MODEL];
__device__ __align__(256) __half g_xl[M_ROWS * C_MODEL];
__device__ __align__(256) __half g_qh[QKD];   // [B,H,T,dk], pre-scaled by 0.125
__device__ __align__(256) __half g_ql[QKD];
__device__ __align__(256) __half g_kh[QKD];   // [B,H,T,dk]  (hi only)
__device__ __align__(256) __half g_vth[QKD];  // [B,H,dk,T]  (V transposed, hi only)
__device__ __align__(256) __half g_yh[M_ROWS * C_MODEL];   // attn out hi
__device__ __align__(256) __half g_yl[M_ROWS * C_MODEL];   // attn out lo
__device__ __align__(256) __half g_wqh[3 * C_MODEL * C_MODEL];  // [3072,1024] (W^T, hi)
__device__ __align__(256) __half g_wph[C_MODEL * C_MODEL];      // [1024,1024] (W^T, hi)

// ------------------------- PTX helpers -------------------------
__device__ __forceinline__ uint32_t smem_u32(const void* p) {
    uint32_t a;
    asm("{ .reg .u64 t; cvta.to.shared.u64 t, %1; cvt.u32.u64 %0, t; }" : "=r"(a) : "l"(p));
    return a;
}
__device__ __forceinline__ void cpasync16(uint32_t dst, const void* src) {
    asm volatile("cp.async.cg.shared.global [%0], [%1], 16;" :: "r"(dst), "l"(src));
}
#define CP_COMMIT() asm volatile("cp.async.commit_group;" ::: "memory")
#define CP_WAIT(n)  asm volatile("cp.async.wait_group %0;" :: "n"(n) : "memory")

__device__ __forceinline__ void ldsm4(uint32_t& r0, uint32_t& r1, uint32_t& r2, uint32_t& r3,
                                      uint32_t addr) {
    asm volatile("ldmatrix.sync.aligned.m8n8.x4.shared.b16 {%0,%1,%2,%3}, [%4];"
                 : "=r"(r0), "=r"(r1), "=r"(r2), "=r"(r3) : "r"(addr));
}
__device__ __forceinline__ void mma16816(float* c, uint32_t a0, uint32_t a1, uint32_t a2,
                                         uint32_t a3, uint32_t b0, uint32_t b1) {
    asm volatile(
        "mma.sync.aligned.m16n8k16.row.col.f32.f16.f16.f32 "
        "{%0,%1,%2,%3}, {%4,%5,%6,%7}, {%8,%9}, {%0,%1,%2,%3};"
        : "+f"(c[0]), "+f"(c[1]), "+f"(c[2]), "+f"(c[3])
        : "r"(a0), "r"(a1), "r"(a2), "r"(a3), "r"(b0), "r"(b1));
}
__device__ __forceinline__ uint32_t packh2(__half a, __half b) {
    __half2 t(a, b);
    return *reinterpret_cast<uint32_t*>(&t);
}
__device__ __forceinline__ void split2h(float a, float b, uint32_t& hi, uint32_t& lo) {
    __half ha = __float2half_rn(a), hb = __float2half_rn(b);
    __half la = __float2half_rn(a - __half2float(ha));
    __half lb = __float2half_rn(b - __half2float(hb));
    hi = packh2(ha, hb);
    lo = packh2(la, lb);
}
__device__ __forceinline__ uint32_t pack2h(float a, float b) {
    __half2 t = __floats2half2_rn(a, b);
    return *reinterpret_cast<uint32_t*>(&t);
}

// ------------------------- conversion kernels -------------------------
__global__ void split_kernel(const float* __restrict__ in,
                             __half* __restrict__ hi,
                             __half* __restrict__ lo, int n4) {
    int i = blockIdx.x * blockDim.x + threadIdx.x;
    if (i >= n4) return;
    float4 v = ((const float4*)in)[i];
    uint32_t h0, l0, h1, l1;
    split2h(v.x, v.y, h0, l0);
    split2h(v.z, v.w, h1, l1);
    ((uint32_t*)hi)[2 * i]     = h0;
    ((uint32_t*)hi)[2 * i + 1] = h1;
    ((uint32_t*)lo)[2 * i]     = l0;
    ((uint32_t*)lo)[2 * i + 1] = l1;
}

// W [K, N] fp32 row-major -> Th [N, K] fp16 (transposed + rounded)
__global__ void transpose_round(const float* __restrict__ W,
                                __half* __restrict__ Th, int K, int N) {
    __shared__ float t[32][33];
    const int bx = blockIdx.x * 32;
    const int by = blockIdx.y * 32;
    const int x = threadIdx.x, y = threadIdx.y;
#pragma unroll
    for (int j = 0; j < 32; j += 8)
        t[y + j][x] = W[(size_t)(by + y + j) * N + bx + x];
    __syncthreads();
#pragma unroll
    for (int j = 0; j < 32; j += 8)
        Th[(size_t)(bx + y + j) * K + by + x] = __float2half_rn(t[x][y + j]);
}

// ------------------------- mma.sync GEMM (fp16, 2-product) -------------------------
// C[8192, NTOT] = (Ah+Al)[8192,1024] @ Bh[NTOT,1024]^T, fp32 accum.
// CTA tile 128x128, K-stage 32, 3-stage cp.async ring, one sync per stage.
// 256 thr = 8 warps in (4 M x 2 N) grid -> warp tile 32x64 (A redundancy 2, B 4).
#define GT_M 128
#define GT_N 128
#define GT_K 32
#define G_NSTAGE 32                  // 1024 / 32
#define ROWB 80                      // 64B data + 16B pad
#define OFF_AH 0
#define OFF_AL (128 * ROWB)          // 10240
#define OFF_BH (2 * 128 * ROWB)      // 20480
#define STAGE_B (3 * 128 * ROWB)     // 30720
#define GEMM_SMEM (3 * STAGE_B)      // 92160

template <int NTOT, int EPI>
__global__ void __launch_bounds__(256, 2) mma_gemm(const __half* __restrict__ Ah_,
                                                   const __half* __restrict__ Al_,
                                                   const __half* __restrict__ Bh_,
                                                   float* __restrict__ C) {
    extern __shared__ char sm[];
    const uint32_t sbase = smem_u32(sm);
    const int tid  = threadIdx.x;
    const int lane = tid & 31;
    const int wid  = tid >> 5;
    const int wm   = wid & 3;          // 0..3  (M blocks of 32)
    const int wn   = wid >> 2;         // 0..1  (N blocks of 64)
    const int row0 = blockIdx.y * GT_M;
    const int col0 = blockIdx.x * GT_N;

    float acc[2][8][4];
#pragma unroll
    for (int i = 0; i < 2; i++)
#pragma unroll
        for (int j = 0; j < 8; j++)
#pragma unroll
            for (int k = 0; k < 4; k++) acc[i][j][k] = 0.f;

    auto load_stage = [&](int kt, int buf) {
        const uint32_t sa = sbase + buf * STAGE_B;
        const int kcol = kt * GT_K;
#pragma unroll
        for (int p = 0; p < 2; p++) {
            const int i = p * 256 + tid, r = i >> 2, c = i & 3;
            cpasync16(sa + OFF_AH + r * ROWB + c * 16,
                      Ah_ + (size_t)(row0 + r) * 1024 + kcol + c * 8);
            cpasync16(sa + OFF_AL + r * ROWB + c * 16,
                      Al_ + (size_t)(row0 + r) * 1024 + kcol + c * 8);
            cpasync16(sa + OFF_BH + r * ROWB + c * 16,
                      Bh_ + (size_t)(col0 + r) * 1024 + kcol + c * 8);
        }
        CP_COMMIT();
    };

    // ldmatrix base addresses (within a stage buffer)
    const uint32_t a_base = OFF_AH + (wm * 32 + (lane & 15)) * ROWB + (lane >> 4) * 16;
    const uint32_t b_base = OFF_BH +
        (wn * 64 + (lane & 7) + ((lane >> 4) << 3)) * ROWB + ((lane >> 3) & 1) * 16;

    load_stage(0, 0);
    load_stage(1, 1);

    for (int kt = 0; kt < G_NSTAGE; kt++) {
        if (kt == G_NSTAGE - 1) { CP_WAIT(0); } else { CP_WAIT(1); }
        __syncthreads();
        if (kt + 2 < G_NSTAGE) load_stage(kt + 2, (kt + 2) % 3);

        const uint32_t sa = sbase + (kt % 3) * STAGE_B;
#pragma unroll
        for (int kk = 0; kk < 2; kk++) {
            const uint32_t koff = kk * 32;
            uint32_t bh[8][2], ah[2][4];
            // B: 8 n8 tiles via 4 ldsm4
#pragma unroll
            for (int p = 0; p < 4; p++)
                ldsm4(bh[2 * p][0], bh[2 * p][1], bh[2 * p + 1][0], bh[2 * p + 1][1],
                      sa + b_base + p * 16 * ROWB + koff);
            // A hi: 2 m16 tiles
#pragma unroll
            for (int mt = 0; mt < 2; mt++)
                ldsm4(ah[mt][0], ah[mt][1], ah[mt][2], ah[mt][3],
                      sa + a_base + mt * 16 * ROWB + koff);
#pragma unroll
            for (int mt = 0; mt < 2; mt++)
#pragma unroll
                for (int nt = 0; nt < 8; nt++)
                    mma16816(acc[mt][nt], ah[mt][0], ah[mt][1], ah[mt][2], ah[mt][3],
                             bh[nt][0], bh[nt][1]);
            // A lo
            {
                uint32_t al[2][4];
#pragma unroll
                for (int mt = 0; mt < 2; mt++)
                    ldsm4(al[mt][0], al[mt][1], al[mt][2], al[mt][3],
                          sa + a_base + (OFF_AL - OFF_AH) + mt * 16 * ROWB + koff);
#pragma unroll
                for (int mt = 0; mt < 2; mt++)
#pragma unroll
                    for (int nt = 0; nt < 8; nt++)
                        mma16816(acc[mt][nt], al[mt][0], al[mt][1], al[mt][2], al[mt][3],
                                 bh[nt][0], bh[nt][1]);
            }
        }
    }

    // epilogue
    const int rbase = lane >> 2;
    const int cpair = (lane & 3) * 2;
#pragma unroll
    for (int mt = 0; mt < 2; mt++) {
#pragma unroll
        for (int nt = 0; nt < 8; nt++) {
            const float* c = acc[mt][nt];
            const int gcol = col0 + wn * 64 + nt * 8 + cpair;
            const int r1 = row0 + wm * 32 + mt * 16 + rbase;
            if constexpr (EPI == 0) {
                *(float2*)&C[(size_t)r1 * NTOT + gcol]       = make_float2(c[0], c[1]);
                *(float2*)&C[(size_t)(r1 + 8) * NTOT + gcol] = make_float2(c[2], c[3]);
            } else {
                const int part = gcol >> 10;       // 0=Q 1=K 2=V
                const int rem  = gcol & 1023;
                const int h = rem >> 6, d = rem & 63;
#pragma unroll
                for (int hh = 0; hh < 2; hh++) {
                    const int gr = r1 + hh * 8;
                    const int b_ = gr >> 10, t_ = gr & 1023;
                    const float v0 = c[hh * 2], v1 = c[hh * 2 + 1];
                    if (part == 0) {
                        uint32_t hi, lo;
                        split2h(v0 * 0.125f, v1 * 0.125f, hi, lo);
                        const size_t o = (((size_t)(b_ * N_HEAD + h)) * T_SEQ + t_) * DK + d;
                        *(uint32_t*)&g_qh[o] = hi;
                        *(uint32_t*)&g_ql[o] = lo;
                    } else if (part == 1) {
                        const size_t o = (((size_t)(b_ * N_HEAD + h)) * T_SEQ + t_) * DK + d;
                        *(uint32_t*)&g_kh[o] = pack2h(v0, v1);
                    } else {
                        // V^T: [B,H,dk,T]
                        const size_t o = (((size_t)(b_ * N_HEAD + h)) * DK + d) * T_SEQ + t_;
                        g_vth[o]         = __float2half_rn(v0);
                        g_vth[o + T_SEQ] = __float2half_rn(v1);
                    }
                }
            }
        }
    }
}

// ------------------------- tensor-core flash attention (fp16) -------------------------
#define AROWB 144
#define ATILE (64 * AROWB)           // 9216
#define AST_KH 0
#define AST_VH ATILE
#define ASTAGE (2 * ATILE)           // 18432
#define AQ_H (2 * ASTAGE)            // 36864
#define AQ_L (AQ_H + ATILE)
#define ATTN_SMEM (AQ_L + ATILE)     // 55296

__global__ void __launch_bounds__(128) attn_kernel() {
    extern __shared__ char sm[];
    const uint32_t sb = smem_u32(sm);
    const int tid  = threadIdx.x;
    const int lane = tid & 31;
    const int w    = tid >> 5;
    const int qt   = (int)gridDim.x - 1 - (int)blockIdx.x;  // long CTAs first
    const int bh   = blockIdx.y;

    const __half* Qh = g_qh + (size_t)bh * (T_SEQ * DK);
    const __half* Ql = g_ql + (size_t)bh * (T_SEQ * DK);
    const __half* Kh = g_kh + (size_t)bh * (T_SEQ * DK);
    const __half* Vh = g_vth + (size_t)bh * (DK * T_SEQ);

    auto load_kv = [&](int kt, int buf) {
        const uint32_t st = sb + buf * ASTAGE;
        const int t0 = kt * 64;
#pragma unroll
        for (int it = 0; it < 4; it++) {
            const int i = it * 128 + tid;
            const int r = i >> 3, c = i & 7;
            cpasync16(st + AST_KH + r * AROWB + c * 16, Kh + (size_t)(t0 + r) * DK + c * 8);
            cpasync16(st + AST_VH + r * AROWB + c * 16, Vh + (size_t)r * T_SEQ + t0 + c * 8);
        }
        CP_COMMIT();
    };

#pragma unroll
    for (int it = 0; it < 4; it++) {
        const int i = it * 128 + tid;
        const int r = i >> 3, c = i & 7;
        cpasync16(sb + AQ_H + r * AROWB + c * 16, Qh + (size_t)(qt * 64 + r) * DK + c * 8);
        cpasync16(sb + AQ_L + r * AROWB + c * 16, Ql + (size_t)(qt * 64 + r) * DK + c * 8);
    }
    CP_COMMIT();
    load_kv(0, 0);

    CP_WAIT(1);
    __syncthreads();

    uint32_t qh[4][4], ql[4][4];
    {
        const uint32_t qa = sb + AQ_H + (w * 16 + (lane & 15)) * AROWB + (lane >> 4) * 16;
#pragma unroll
        for (int ks = 0; ks < 4; ks++) {
            ldsm4(qh[ks][0], qh[ks][1], qh[ks][2], qh[ks][3], qa + ks * 32);
            ldsm4(ql[ks][0], ql[ks][1], ql[ks][2], ql[ks][3], qa + (AQ_L - AQ_H) + ks * 32);
        }
    }

    float O[8][4];
#pragma unroll
    for (int i = 0; i < 8; i++)
#pragma unroll
        for (int j = 0; j < 4; j++) O[i][j] = 0.f;
    float m0 = -3.0e38f, m1 = -3.0e38f, l0 = 0.f, l1 = 0.f;

    const uint32_t bpat = ((lane & 7) + ((lane >> 4) << 3)) * AROWB + ((lane >> 3) & 1) * 16;

    for (int kt = 0; kt <= qt; kt++) {
        if (kt < qt) { load_kv(kt + 1, (kt + 1) & 1); CP_WAIT(1); } else { CP_WAIT(0); }
        __syncthreads();
        const uint32_t st = sb + (kt & 1) * ASTAGE;

        float S[8][4];
#pragma unroll
        for (int i = 0; i < 8; i++)
#pragma unroll
            for (int j = 0; j < 4; j++) S[i][j] = 0.f;

#pragma unroll
        for (int ks = 0; ks < 4; ks++) {
            uint32_t kh[8][2];
#pragma unroll
            for (int p = 0; p < 4; p++)
                ldsm4(kh[2 * p][0], kh[2 * p][1], kh[2 * p + 1][0], kh[2 * p + 1][1],
                      st + AST_KH + p * 16 * AROWB + bpat + ks * 32);
#pragma unroll
            for (int nt = 0; nt < 8; nt++) {
                mma16816(S[nt], qh[ks][0], qh[ks][1], qh[ks][2], qh[ks][3], kh[nt][0], kh[nt][1]);
                mma16816(S[nt], ql[ks][0], ql[ks][1], ql[ks][2], ql[ks][3], kh[nt][0], kh[nt][1]);
            }
        }

        if (kt == qt) {
            const int grow = qt * 64 + w * 16 + (lane >> 2);
#pragma unroll
            for (int nt = 0; nt < 8; nt++) {
                const int col = qt * 64 + nt * 8 + (lane & 3) * 2;
                if (col     > grow)     S[nt][0] = -3.0e38f;
                if (col + 1 > grow)     S[nt][1] = -3.0e38f;
                if (col     > grow + 8) S[nt][2] = -3.0e38f;
                if (col + 1 > grow + 8) S[nt][3] = -3.0e38f;
            }
        }

        float mx0 = -3.0e38f, mx1 = -3.0e38f;
#pragma unroll
        for (int nt = 0; nt < 8; nt++) {
            mx0 = fmaxf(mx0, fmaxf(S[nt][0], S[nt][1]));
            mx1 = fmaxf(mx1, fmaxf(S[nt][2], S[nt][3]));
        }
        mx0 = fmaxf(mx0, __shfl_xor_sync(0xffffffffu, mx0, 1));
        mx0 = fmaxf(mx0, __shfl_xor_sync(0xffffffffu, mx0, 2));
        mx1 = fmaxf(mx1, __shfl_xor_sync(0xffffffffu, mx1, 1));
        mx1 = fmaxf(mx1, __shfl_xor_sync(0xffffffffu, mx1, 2));
        const float mn0 = fmaxf(m0, mx0);
        const float mn1 = fmaxf(m1, mx1);
        const float sc0 = __expf(m0 - mn0);
        const float sc1 = __expf(m1 - mn1);
        float sum0 = 0.f, sum1 = 0.f;
#pragma unroll
        for (int nt = 0; nt < 8; nt++) {
            S[nt][0] = __expf(S[nt][0] - mn0); sum0 += S[nt][0];
            S[nt][1] = __expf(S[nt][1] - mn0); sum0 += S[nt][1];
            S[nt][2] = __expf(S[nt][2] - mn1); sum1 += S[nt][2];
            S[nt][3] = __expf(S[nt][3] - mn1); sum1 += S[nt][3];
        }
        sum0 += __shfl_xor_sync(0xffffffffu, sum0, 1);
        sum0 += __shfl_xor_sync(0xffffffffu, sum0, 2);
        sum1 += __shfl_xor_sync(0xffffffffu, sum1, 1);
        sum1 += __shfl_xor_sync(0xffffffffu, sum1, 2);
        l0 = l0 * sc0 + sum0;
        l1 = l1 * sc1 + sum1;
        m0 = mn0; m1 = mn1;
#pragma unroll
        for (int nt = 0; nt < 8; nt++) {
            O[nt][0] *= sc0; O[nt][1] *= sc0;
            O[nt][2] *= sc1; O[nt][3] *= sc1;
        }

#pragma unroll
        for (int ks = 0; ks < 4; ks++) {
            uint32_t pa[4];
            pa[0] = pack2h(S[2 * ks][0],     S[2 * ks][1]);
            pa[1] = pack2h(S[2 * ks][2],     S[2 * ks][3]);
            pa[2] = pack2h(S[2 * ks + 1][0], S[2 * ks + 1][1]);
            pa[3] = pack2h(S[2 * ks + 1][2], S[2 * ks + 1][3]);
            uint32_t vh[8][2];
#pragma unroll
            for (int p = 0; p < 4; p++)
                ldsm4(vh[2 * p][0], vh[2 * p][1], vh[2 * p + 1][0], vh[2 * p + 1][1],
                      st + AST_VH + p * 16 * AROWB + bpat + ks * 32);
#pragma unroll
            for (int nt = 0; nt < 8; nt++)
                mma16816(O[nt], pa[0], pa[1], pa[2], pa[3], vh[nt][0], vh[nt][1]);
        }
        __syncthreads();
    }

    const float inv0 = 1.0f / l0;
    const float inv1 = 1.0f / l1;
    const int b_ = bh >> 4, h_ = bh & 15;
    const int t0 = qt * 64 + w * 16 + (lane >> 2);
#pragma unroll
    for (int nt = 0; nt < 8; nt++) {
        const int d = nt * 8 + (lane & 3) * 2;
        uint32_t hi, lo;
        split2h(O[nt][0] * inv0, O[nt][1] * inv0, hi, lo);
        size_t o = ((size_t)(b_ * T_SEQ + t0)) * C_MODEL + h_ * DK + d;
        *(uint32_t*)&g_yh[o] = hi;
        *(uint32_t*)&g_yl[o] = lo;
        split2h(O[nt][2] * inv1, O[nt][3] * inv1, hi, lo);
        o = ((size_t)(b_ * T_SEQ + t0 + 8)) * C_MODEL + h_ * DK + d;
        *(uint32_t*)&g_yh[o] = hi;
        *(uint32_t*)&g_yl[o] = lo;
    }
}

// ---------------------------------------------------------------------------

extern "C" void kernel_launch(void* const* d_in, const int* in_sizes, int n_in,
                              void* d_out, int out_size) {
    const float* x     = (const float*)d_in[0];   // [8,1024,1024]
    const float* wqkv  = (const float*)d_in[1];   // [1024,3072]
    const float* wproj = (const float*)d_in[2];   // [1024,1024]
    float* out = (float*)d_out;                   // [8,1024,1024]

    cudaFuncSetAttribute(attn_kernel,
                         cudaFuncAttributeMaxDynamicSharedMemorySize, ATTN_SMEM);
    cudaFuncSetAttribute(mma_gemm<3072, 1>,
                         cudaFuncAttributeMaxDynamicSharedMemorySize, GEMM_SMEM);
    cudaFuncSetAttribute(mma_gemm<1024, 0>,
                         cudaFuncAttributeMaxDynamicSharedMemorySize, GEMM_SMEM);

    __half *xh, *xl, *yh, *yl, *wqh, *wph;
    cudaGetSymbolAddress((void**)&xh,  g_xh);
    cudaGetSymbolAddress((void**)&xl,  g_xl);
    cudaGetSymbolAddress((void**)&yh,  g_yh);
    cudaGetSymbolAddress((void**)&yl,  g_yl);
    cudaGetSymbolAddress((void**)&wqh, g_wqh);
    cudaGetSymbolAddress((void**)&wph, g_wph);

    split_kernel<<<(M_ROWS * C_MODEL / 4 + 255) / 256, 256>>>(x, xh, xl, M_ROWS * C_MODEL / 4);
    transpose_round<<<dim3(3072 / 32, 1024 / 32), dim3(32, 8)>>>(wqkv, wqh, 1024, 3072);
    transpose_round<<<dim3(1024 / 32, 1024 / 32), dim3(32, 8)>>>(wproj, wph, 1024, 1024);

    mma_gemm<3072, 1><<<dim3(3072 / GT_N, M_ROWS / GT_M), 256, GEMM_SMEM>>>(
        xh, xl, wqh, nullptr);

    attn_kernel<<<dim3(T_SEQ / 64, N_BATCH * N_HEAD), 128, ATTN_SMEM>>>();

    mma_gemm<1024, 0><<<dim3(1024 / GT_N, M_ROWS / GT_M), 256, GEMM_SMEM>>>(
        yh, yl, wph, out);
}

// round 7
// speedup vs baseline: 5.6411x; 1.4335x over previous
#include <cuda_runtime.h>
#include <cuda_fp16.h>
#include <cstdint>
#include <math.h>

// Problem constants
#define C_MODEL 1024
#define N_HEAD  16
#define DK      64
#define T_SEQ   1024
#define N_BATCH 8
#define M_ROWS  (N_BATCH * T_SEQ)   // 8192
#define QKD     (N_BATCH * N_HEAD * T_SEQ * DK)   // 8388608

// ------------------------- scratch (device globals) -------------------------
__device__ __align__(256) __half g_xh[M_ROWS * C_MODEL];        // x rounded
__device__ __align__(256) __half g_qh[QKD];   // [B,H,T,dk], pre-scaled by 0.125
__device__ __align__(256) __half g_kh[QKD];   // [B,H,T,dk]
__device__ __align__(256) __half g_vth[QKD];  // [B,H,dk,T]  (V transposed)
__device__ __align__(256) __half g_yh[M_ROWS * C_MODEL];   // attn out hi
__device__ __align__(256) __half g_yl[M_ROWS * C_MODEL];   // attn out lo
__device__ __align__(256) __half g_wqh[3 * C_MODEL * C_MODEL];  // [3072,1024] (W^T)
__device__ __align__(256) __half g_wph[C_MODEL * C_MODEL];      // [1024,1024] (W^T)

// ------------------------- PTX helpers -------------------------
__device__ __forceinline__ uint32_t smem_u32(const void* p) {
    uint32_t a;
    asm("{ .reg .u64 t; cvta.to.shared.u64 t, %1; cvt.u32.u64 %0, t; }" : "=r"(a) : "l"(p));
    return a;
}
__device__ __forceinline__ void cpasync16(uint32_t dst, const void* src) {
    asm volatile("cp.async.cg.shared.global [%0], [%1], 16;" :: "r"(dst), "l"(src));
}
#define CP_COMMIT() asm volatile("cp.async.commit_group;" ::: "memory")
#define CP_WAIT(n)  asm volatile("cp.async.wait_group %0;" :: "n"(n) : "memory")

__device__ __forceinline__ void ldsm4(uint32_t& r0, uint32_t& r1, uint32_t& r2, uint32_t& r3,
                                      uint32_t addr) {
    asm volatile("ldmatrix.sync.aligned.m8n8.x4.shared.b16 {%0,%1,%2,%3}, [%4];"
                 : "=r"(r0), "=r"(r1), "=r"(r2), "=r"(r3) : "r"(addr));
}
__device__ __forceinline__ void mma16816(float* c, uint32_t a0, uint32_t a1, uint32_t a2,
                                         uint32_t a3, uint32_t b0, uint32_t b1) {
    asm volatile(
        "mma.sync.aligned.m16n8k16.row.col.f32.f16.f16.f32 "
        "{%0,%1,%2,%3}, {%4,%5,%6,%7}, {%8,%9}, {%0,%1,%2,%3};"
        : "+f"(c[0]), "+f"(c[1]), "+f"(c[2]), "+f"(c[3])
        : "r"(a0), "r"(a1), "r"(a2), "r"(a3), "r"(b0), "r"(b1));
}
__device__ __forceinline__ uint32_t packh2(__half a, __half b) {
    __half2 t(a, b);
    return *reinterpret_cast<uint32_t*>(&t);
}
__device__ __forceinline__ void split2h(float a, float b, uint32_t& hi, uint32_t& lo) {
    __half ha = __float2half_rn(a), hb = __float2half_rn(b);
    __half la = __float2half_rn(a - __half2float(ha));
    __half lb = __float2half_rn(b - __half2float(hb));
    hi = packh2(ha, hb);
    lo = packh2(la, lb);
}
__device__ __forceinline__ uint32_t pack2h(float a, float b) {
    __half2 t = __floats2half2_rn(a, b);
    return *reinterpret_cast<uint32_t*>(&t);
}

// ------------------------- conversion kernels -------------------------
// fp32 -> fp16 rounding (no split)
__global__ void round_kernel(const float* __restrict__ in,
                             __half* __restrict__ hi, int n4) {
    int i = blockIdx.x * blockDim.x + threadIdx.x;
    if (i >= n4) return;
    float4 v = ((const float4*)in)[i];
    ((uint32_t*)hi)[2 * i]     = pack2h(v.x, v.y);
    ((uint32_t*)hi)[2 * i + 1] = pack2h(v.z, v.w);
}

// W [K, N] fp32 row-major -> Th [N, K] fp16 (transposed + rounded)
__global__ void transpose_round(const float* __restrict__ W,
                                __half* __restrict__ Th, int K, int N) {
    __shared__ float t[32][33];
    const int bx = blockIdx.x * 32;
    const int by = blockIdx.y * 32;
    const int x = threadIdx.x, y = threadIdx.y;
#pragma unroll
    for (int j = 0; j < 32; j += 8)
        t[y + j][x] = W[(size_t)(by + y + j) * N + bx + x];
    __syncthreads();
#pragma unroll
    for (int j = 0; j < 32; j += 8)
        Th[(size_t)(bx + y + j) * K + by + x] = __float2half_rn(t[x][y + j]);
}

// ===================== QKV GEMM: fp16 1-product, K-stage 64, 3-ring =====================
// qkv[8192, 3072] = xh[8192,1024] @ wqh[3072,1024]^T, fp32 accum.
// CTA tile 128x128; 256 thr = 8 warps (4M x 2N), warp 32x64. 2 CTAs/SM.
#define QK_ROWB 144                    // 128B data + 16B pad
#define QK_OFFB (128 * QK_ROWB)        // 18432 (B tile offset)
#define QK_STAGE (2 * 128 * QK_ROWB)   // 36864
#define QK_SMEM (3 * QK_STAGE)         // 110592
#define QK_NST 16                      // 1024 / 64

__global__ void __launch_bounds__(256, 2) qkv_gemm(const __half* __restrict__ Ah_,
                                                   const __half* __restrict__ Bh_) {
    extern __shared__ char sm[];
    const uint32_t sbase = smem_u32(sm);
    const int tid  = threadIdx.x;
    const int lane = tid & 31;
    const int wid  = tid >> 5;
    const int wm   = wid & 3;          // 0..3 (M blocks of 32)
    const int wn   = wid >> 2;         // 0..1 (N blocks of 64)
    const int row0 = blockIdx.y * 128;
    const int col0 = blockIdx.x * 128;

    float acc[2][8][4];
#pragma unroll
    for (int i = 0; i < 2; i++)
#pragma unroll
        for (int j = 0; j < 8; j++)
#pragma unroll
            for (int k = 0; k < 4; k++) acc[i][j][k] = 0.f;

    auto load_stage = [&](int kt, int buf) {
        const uint32_t sa = sbase + buf * QK_STAGE;
        const int kcol = kt * 64;
        // A: 128 rows x 128B = 1024 chunks; B same; 8 chunks/thread total
#pragma unroll
        for (int p = 0; p < 4; p++) {
            const int i = p * 256 + tid, r = i >> 3, c = i & 7;
            cpasync16(sa + r * QK_ROWB + c * 16,
                      Ah_ + (size_t)(row0 + r) * 1024 + kcol + c * 8);
            cpasync16(sa + QK_OFFB + r * QK_ROWB + c * 16,
                      Bh_ + (size_t)(col0 + r) * 1024 + kcol + c * 8);
        }
        CP_COMMIT();
    };

    const uint32_t a_base = (wm * 32 + (lane & 15)) * QK_ROWB + (lane >> 4) * 16;
    const uint32_t b_base = QK_OFFB +
        (wn * 64 + (lane & 7) + ((lane >> 4) << 3)) * QK_ROWB + ((lane >> 3) & 1) * 16;

    load_stage(0, 0);
    load_stage(1, 1);

    for (int kt = 0; kt < QK_NST; kt++) {
        if (kt == QK_NST - 1) { CP_WAIT(0); } else { CP_WAIT(1); }
        __syncthreads();
        if (kt + 2 < QK_NST) load_stage(kt + 2, (kt + 2) % 3);

        const uint32_t sa = sbase + (kt % 3) * QK_STAGE;
#pragma unroll
        for (int ks = 0; ks < 4; ks++) {
            const uint32_t koff = ks * 32;
            uint32_t ah[2][4], bh[8][2];
#pragma unroll
            for (int mt = 0; mt < 2; mt++)
                ldsm4(ah[mt][0], ah[mt][1], ah[mt][2], ah[mt][3],
                      sa + a_base + mt * 16 * QK_ROWB + koff);
#pragma unroll
            for (int p = 0; p < 4; p++)
                ldsm4(bh[2 * p][0], bh[2 * p][1], bh[2 * p + 1][0], bh[2 * p + 1][1],
                      sa + b_base + p * 16 * QK_ROWB + koff);
#pragma unroll
            for (int mt = 0; mt < 2; mt++)
#pragma unroll
                for (int nt = 0; nt < 8; nt++)
                    mma16816(acc[mt][nt], ah[mt][0], ah[mt][1], ah[mt][2], ah[mt][3],
                             bh[nt][0], bh[nt][1]);
        }
    }

    // epilogue: scatter q(scaled)/k/v^T as fp16
    const int rbase = lane >> 2;
    const int cpair = (lane & 3) * 2;
#pragma unroll
    for (int mt = 0; mt < 2; mt++) {
#pragma unroll
        for (int nt = 0; nt < 8; nt++) {
            const float* c = acc[mt][nt];
            const int gcol = col0 + wn * 64 + nt * 8 + cpair;
            const int part = gcol >> 10;       // 0=Q 1=K 2=V
            const int rem  = gcol & 1023;
            const int h = rem >> 6, d = rem & 63;
            const int r1 = row0 + wm * 32 + mt * 16 + rbase;
#pragma unroll
            for (int hh = 0; hh < 2; hh++) {
                const int gr = r1 + hh * 8;
                const int b_ = gr >> 10, t_ = gr & 1023;
                const float v0 = c[hh * 2], v1 = c[hh * 2 + 1];
                if (part == 0) {
                    const size_t o = (((size_t)(b_ * N_HEAD + h)) * T_SEQ + t_) * DK + d;
                    *(uint32_t*)&g_qh[o] = pack2h(v0 * 0.125f, v1 * 0.125f);
                } else if (part == 1) {
                    const size_t o = (((size_t)(b_ * N_HEAD + h)) * T_SEQ + t_) * DK + d;
                    *(uint32_t*)&g_kh[o] = pack2h(v0, v1);
                } else {
                    const size_t o = (((size_t)(b_ * N_HEAD + h)) * DK + d) * T_SEQ + t_;
                    g_vth[o]         = __float2half_rn(v0);
                    g_vth[o + T_SEQ] = __float2half_rn(v1);
                }
            }
        }
    }
}

// ===================== proj GEMM: fp16 2-product, K-stage 32, 3-ring =====================
// out[8192,1024] = (yh+yl)[8192,1024] @ wph[1024,1024]^T, fp32 accum.
#define GT_N 128
#define G_NSTAGE 32
#define ROWB 80
#define OFF_AH 0
#define OFF_AL (128 * ROWB)
#define OFF_BH (2 * 128 * ROWB)
#define STAGE_B (3 * 128 * ROWB)     // 30720
#define GEMM_SMEM (3 * STAGE_B)      // 92160

__global__ void __launch_bounds__(256, 2) proj_gemm(const __half* __restrict__ Ah_,
                                                    const __half* __restrict__ Al_,
                                                    const __half* __restrict__ Bh_,
                                                    float* __restrict__ C) {
    extern __shared__ char sm[];
    const uint32_t sbase = smem_u32(sm);
    const int tid  = threadIdx.x;
    const int lane = tid & 31;
    const int wid  = tid >> 5;
    const int wm   = wid & 3;
    const int wn   = wid >> 2;
    const int row0 = blockIdx.y * 128;
    const int col0 = blockIdx.x * 128;

    float acc[2][8][4];
#pragma unroll
    for (int i = 0; i < 2; i++)
#pragma unroll
        for (int j = 0; j < 8; j++)
#pragma unroll
            for (int k = 0; k < 4; k++) acc[i][j][k] = 0.f;

    auto load_stage = [&](int kt, int buf) {
        const uint32_t sa = sbase + buf * STAGE_B;
        const int kcol = kt * 32;
#pragma unroll
        for (int p = 0; p < 2; p++) {
            const int i = p * 256 + tid, r = i >> 2, c = i & 3;
            cpasync16(sa + OFF_AH + r * ROWB + c * 16,
                      Ah_ + (size_t)(row0 + r) * 1024 + kcol + c * 8);
            cpasync16(sa + OFF_AL + r * ROWB + c * 16,
                      Al_ + (size_t)(row0 + r) * 1024 + kcol + c * 8);
            cpasync16(sa + OFF_BH + r * ROWB + c * 16,
                      Bh_ + (size_t)(col0 + r) * 1024 + kcol + c * 8);
        }
        CP_COMMIT();
    };

    const uint32_t a_base = OFF_AH + (wm * 32 + (lane & 15)) * ROWB + (lane >> 4) * 16;
    const uint32_t b_base = OFF_BH +
        (wn * 64 + (lane & 7) + ((lane >> 4) << 3)) * ROWB + ((lane >> 3) & 1) * 16;

    load_stage(0, 0);
    load_stage(1, 1);

    for (int kt = 0; kt < G_NSTAGE; kt++) {
        if (kt == G_NSTAGE - 1) { CP_WAIT(0); } else { CP_WAIT(1); }
        __syncthreads();
        if (kt + 2 < G_NSTAGE) load_stage(kt + 2, (kt + 2) % 3);

        const uint32_t sa = sbase + (kt % 3) * STAGE_B;
#pragma unroll
        for (int kk = 0; kk < 2; kk++) {
            const uint32_t koff = kk * 32;
            uint32_t bh[8][2], ah[2][4];
#pragma unroll
            for (int p = 0; p < 4; p++)
                ldsm4(bh[2 * p][0], bh[2 * p][1], bh[2 * p + 1][0], bh[2 * p + 1][1],
                      sa + b_base + p * 16 * ROWB + koff);
#pragma unroll
            for (int mt = 0; mt < 2; mt++)
                ldsm4(ah[mt][0], ah[mt][1], ah[mt][2], ah[mt][3],
                      sa + a_base + mt * 16 * ROWB + koff);
#pragma unroll
            for (int mt = 0; mt < 2; mt++)
#pragma unroll
                for (int nt = 0; nt < 8; nt++)
                    mma16816(acc[mt][nt], ah[mt][0], ah[mt][1], ah[mt][2], ah[mt][3],
                             bh[nt][0], bh[nt][1]);
            {
                uint32_t al[2][4];
#pragma unroll
                for (int mt = 0; mt < 2; mt++)
                    ldsm4(al[mt][0], al[mt][1], al[mt][2], al[mt][3],
                          sa + a_base + (OFF_AL - OFF_AH) + mt * 16 * ROWB + koff);
#pragma unroll
                for (int mt = 0; mt < 2; mt++)
#pragma unroll
                    for (int nt = 0; nt < 8; nt++)
                        mma16816(acc[mt][nt], al[mt][0], al[mt][1], al[mt][2], al[mt][3],
                                 bh[nt][0], bh[nt][1]);
            }
        }
    }

    const int rbase = lane >> 2;
    const int cpair = (lane & 3) * 2;
#pragma unroll
    for (int mt = 0; mt < 2; mt++) {
#pragma unroll
        for (int nt = 0; nt < 8; nt++) {
            const float* c = acc[mt][nt];
            const int gcol = col0 + wn * 64 + nt * 8 + cpair;
            const int r1 = row0 + wm * 32 + mt * 16 + rbase;
            *(float2*)&C[(size_t)r1 * 1024 + gcol]       = make_float2(c[0], c[1]);
            *(float2*)&C[(size_t)(r1 + 8) * 1024 + gcol] = make_float2(c[2], c[3]);
        }
    }
}

// ------------------------- tensor-core flash attention (fp16, 1-product S) ------------
#define AROWB 144
#define ATILE (64 * AROWB)           // 9216
#define AST_KH 0
#define AST_VH ATILE
#define ASTAGE (2 * ATILE)           // 18432
#define AQ_H (2 * ASTAGE)            // 36864
#define ATTN_SMEM (AQ_H + ATILE)     // 46080

__global__ void __launch_bounds__(128) attn_kernel() {
    extern __shared__ char sm[];
    const uint32_t sb = smem_u32(sm);
    const int tid  = threadIdx.x;
    const int lane = tid & 31;
    const int w    = tid >> 5;
    const int qt   = (int)gridDim.x - 1 - (int)blockIdx.x;  // long CTAs first
    const int bh   = blockIdx.y;

    const __half* Qh = g_qh + (size_t)bh * (T_SEQ * DK);
    const __half* Kh = g_kh + (size_t)bh * (T_SEQ * DK);
    const __half* Vh = g_vth + (size_t)bh * (DK * T_SEQ);

    auto load_kv = [&](int kt, int buf) {
        const uint32_t st = sb + buf * ASTAGE;
        const int t0 = kt * 64;
#pragma unroll
        for (int it = 0; it < 4; it++) {
            const int i = it * 128 + tid;
            const int r = i >> 3, c = i & 7;
            cpasync16(st + AST_KH + r * AROWB + c * 16, Kh + (size_t)(t0 + r) * DK + c * 8);
            cpasync16(st + AST_VH + r * AROWB + c * 16, Vh + (size_t)r * T_SEQ + t0 + c * 8);
        }
        CP_COMMIT();
    };

#pragma unroll
    for (int it = 0; it < 4; it++) {
        const int i = it * 128 + tid;
        const int r = i >> 3, c = i & 7;
        cpasync16(sb + AQ_H + r * AROWB + c * 16, Qh + (size_t)(qt * 64 + r) * DK + c * 8);
    }
    CP_COMMIT();
    load_kv(0, 0);

    CP_WAIT(1);
    __syncthreads();

    uint32_t qh[4][4];
    {
        const uint32_t qa = sb + AQ_H + (w * 16 + (lane & 15)) * AROWB + (lane >> 4) * 16;
#pragma unroll
        for (int ks = 0; ks < 4; ks++)
            ldsm4(qh[ks][0], qh[ks][1], qh[ks][2], qh[ks][3], qa + ks * 32);
    }

    float O[8][4];
#pragma unroll
    for (int i = 0; i < 8; i++)
#pragma unroll
        for (int j = 0; j < 4; j++) O[i][j] = 0.f;
    float m0 = -3.0e38f, m1 = -3.0e38f, l0 = 0.f, l1 = 0.f;

    const uint32_t bpat = ((lane & 7) + ((lane >> 4) << 3)) * AROWB + ((lane >> 3) & 1) * 16;

    for (int kt = 0; kt <= qt; kt++) {
        if (kt < qt) { load_kv(kt + 1, (kt + 1) & 1); CP_WAIT(1); } else { CP_WAIT(0); }
        __syncthreads();
        const uint32_t st = sb + (kt & 1) * ASTAGE;

        float S[8][4];
#pragma unroll
        for (int i = 0; i < 8; i++)
#pragma unroll
            for (int j = 0; j < 4; j++) S[i][j] = 0.f;

#pragma unroll
        for (int ks = 0; ks < 4; ks++) {
            uint32_t kh[8][2];
#pragma unroll
            for (int p = 0; p < 4; p++)
                ldsm4(kh[2 * p][0], kh[2 * p][1], kh[2 * p + 1][0], kh[2 * p + 1][1],
                      st + AST_KH + p * 16 * AROWB + bpat + ks * 32);
#pragma unroll
            for (int nt = 0; nt < 8; nt++)
                mma16816(S[nt], qh[ks][0], qh[ks][1], qh[ks][2], qh[ks][3], kh[nt][0], kh[nt][1]);
        }

        if (kt == qt) {
            const int grow = qt * 64 + w * 16 + (lane >> 2);
#pragma unroll
            for (int nt = 0; nt < 8; nt++) {
                const int col = qt * 64 + nt * 8 + (lane & 3) * 2;
                if (col     > grow)     S[nt][0] = -3.0e38f;
                if (col + 1 > grow)     S[nt][1] = -3.0e38f;
                if (col     > grow + 8) S[nt][2] = -3.0e38f;
                if (col + 1 > grow + 8) S[nt][3] = -3.0e38f;
            }
        }

        float mx0 = -3.0e38f, mx1 = -3.0e38f;
#pragma unroll
        for (int nt = 0; nt < 8; nt++) {
            mx0 = fmaxf(mx0, fmaxf(S[nt][0], S[nt][1]));
            mx1 = fmaxf(mx1, fmaxf(S[nt][2], S[nt][3]));
        }
        mx0 = fmaxf(mx0, __shfl_xor_sync(0xffffffffu, mx0, 1));
        mx0 = fmaxf(mx0, __shfl_xor_sync(0xffffffffu, mx0, 2));
        mx1 = fmaxf(mx1, __shfl_xor_sync(0xffffffffu, mx1, 1));
        mx1 = fmaxf(mx1, __shfl_xor_sync(0xffffffffu, mx1, 2));
        const float mn0 = fmaxf(m0, mx0);
        const float mn1 = fmaxf(m1, mx1);
        const float sc0 = __expf(m0 - mn0);
        const float sc1 = __expf(m1 - mn1);
        float sum0 = 0.f, sum1 = 0.f;
#pragma unroll
        for (int nt = 0; nt < 8; nt++) {
            S[nt][0] = __expf(S[nt][0] - mn0); sum0 += S[nt][0];
            S[nt][1] = __expf(S[nt][1] - mn0); sum0 += S[nt][1];
            S[nt][2] = __expf(S[nt][2] - mn1); sum1 += S[nt][2];
            S[nt][3] = __expf(S[nt][3] - mn1); sum1 += S[nt][3];
        }
        sum0 += __shfl_xor_sync(0xffffffffu, sum0, 1);
        sum0 += __shfl_xor_sync(0xffffffffu, sum0, 2);
        sum1 += __shfl_xor_sync(0xffffffffu, sum1, 1);
        sum1 += __shfl_xor_sync(0xffffffffu, sum1, 2);
        l0 = l0 * sc0 + sum0;
        l1 = l1 * sc1 + sum1;
        m0 = mn0; m1 = mn1;
#pragma unroll
        for (int nt = 0; nt < 8; nt++) {
            O[nt][0] *= sc0; O[nt][1] *= sc0;
            O[nt][2] *= sc1; O[nt][3] *= sc1;
        }

#pragma unroll
        for (int ks = 0; ks < 4; ks++) {
            uint32_t pa[4];
            pa[0] = pack2h(S[2 * ks][0],     S[2 * ks][1]);
            pa[1] = pack2h(S[2 * ks][2],     S[2 * ks][3]);
            pa[2] = pack2h(S[2 * ks + 1][0], S[2 * ks + 1][1]);
            pa[3] = pack2h(S[2 * ks + 1][2], S[2 * ks + 1][3]);
            uint32_t vh[8][2];
#pragma unroll
            for (int p = 0; p < 4; p++)
                ldsm4(vh[2 * p][0], vh[2 * p][1], vh[2 * p + 1][0], vh[2 * p + 1][1],
                      st + AST_VH + p * 16 * AROWB + bpat + ks * 32);
#pragma unroll
            for (int nt = 0; nt < 8; nt++)
                mma16816(O[nt], pa[0], pa[1], pa[2], pa[3], vh[nt][0], vh[nt][1]);
        }
        __syncthreads();
    }

    const float inv0 = 1.0f / l0;
    const float inv1 = 1.0f / l1;
    const int b_ = bh >> 4, h_ = bh & 15;
    const int t0 = qt * 64 + w * 16 + (lane >> 2);
#pragma unroll
    for (int nt = 0; nt < 8; nt++) {
        const int d = nt * 8 + (lane & 3) * 2;
        uint32_t hi, lo;
        split2h(O[nt][0] * inv0, O[nt][1] * inv0, hi, lo);
        size_t o = ((size_t)(b_ * T_SEQ + t0)) * C_MODEL + h_ * DK + d;
        *(uint32_t*)&g_yh[o] = hi;
        *(uint32_t*)&g_yl[o] = lo;
        split2h(O[nt][2] * inv1, O[nt][3] * inv1, hi, lo);
        o = ((size_t)(b_ * T_SEQ + t0 + 8)) * C_MODEL + h_ * DK + d;
        *(uint32_t*)&g_yh[o] = hi;
        *(uint32_t*)&g_yl[o] = lo;
    }
}

// ---------------------------------------------------------------------------

extern "C" void kernel_launch(void* const* d_in, const int* in_sizes, int n_in,
                              void* d_out, int out_size) {
    const float* x     = (const float*)d_in[0];   // [8,1024,1024]
    const float* wqkv  = (const float*)d_in[1];   // [1024,3072]
    const float* wproj = (const float*)d_in[2];   // [1024,1024]
    float* out = (float*)d_out;                   // [8,1024,1024]

    cudaFuncSetAttribute(attn_kernel,
                         cudaFuncAttributeMaxDynamicSharedMemorySize, ATTN_SMEM);
    cudaFuncSetAttribute(qkv_gemm,
                         cudaFuncAttributeMaxDynamicSharedMemorySize, QK_SMEM);
    cudaFuncSetAttribute(proj_gemm,
                         cudaFuncAttributeMaxDynamicSharedMemorySize, GEMM_SMEM);

    __half *xh, *yh, *yl, *wqh, *wph;
    cudaGetSymbolAddress((void**)&xh,  g_xh);
    cudaGetSymbolAddress((void**)&yh,  g_yh);
    cudaGetSymbolAddress((void**)&yl,  g_yl);
    cudaGetSymbolAddress((void**)&wqh, g_wqh);
    cudaGetSymbolAddress((void**)&wph, g_wph);

    // 1) conversions
    round_kernel<<<(M_ROWS * C_MODEL / 4 + 255) / 256, 256>>>(x, xh, M_ROWS * C_MODEL / 4);
    transpose_round<<<dim3(3072 / 32, 1024 / 32), dim3(32, 8)>>>(wqkv, wqh, 1024, 3072);
    transpose_round<<<dim3(1024 / 32, 1024 / 32), dim3(32, 8)>>>(wproj, wph, 1024, 1024);

    // 2) QKV projection (1-product) -> q(scaled)/k/v^T fp16
    qkv_gemm<<<dim3(3072 / 128, M_ROWS / 128), 256, QK_SMEM>>>(xh, wqh);

    // 3) tensor-core causal attention -> y hi/lo
    attn_kernel<<<dim3(T_SEQ / 64, N_BATCH * N_HEAD), 128, ATTN_SMEM>>>();

    // 4) output projection (2-product, protects the direct path)
    proj_gemm<<<dim3(1024 / 128, M_ROWS / 128), 256, GEMM_SMEM>>>(yh, yl, wph, out);
}

// round 8
// speedup vs baseline: 6.6376x; 1.1767x over previous
#include <cuda_runtime.h>
#include <cuda_fp16.h>
#include <cstdint>
#include <math.h>

// Problem constants
#define C_MODEL 1024
#define N_HEAD  16
#define DK      64
#define T_SEQ   1024
#define N_BATCH 8
#define M_ROWS  (N_BATCH * T_SEQ)   // 8192
#define QKD     (N_BATCH * N_HEAD * T_SEQ * DK)   // 8388608

// ------------------------- scratch (device globals) -------------------------
__device__ __align__(256) __half g_xh[M_ROWS * C_MODEL];        // x rounded
__device__ __align__(256) __half g_qh[QKD];   // [B,H,T,dk], pre-scaled by 0.125
__device__ __align__(256) __half g_kh[QKD];   // [B,H,T,dk]
__device__ __align__(256) __half g_vth[QKD];  // [B,H,dk,T]  (V transposed)
__device__ __align__(256) __half g_yh[M_ROWS * C_MODEL];        // attn out (fp16)
__device__ __align__(256) __half g_wqh[3 * C_MODEL * C_MODEL];  // [3072,1024] (W^T)
__device__ __align__(256) __half g_wph[C_MODEL * C_MODEL];      // [1024,1024] (W^T)

// ------------------------- PTX helpers -------------------------
__device__ __forceinline__ uint32_t smem_u32(const void* p) {
    uint32_t a;
    asm("{ .reg .u64 t; cvta.to.shared.u64 t, %1; cvt.u32.u64 %0, t; }" : "=r"(a) : "l"(p));
    return a;
}
__device__ __forceinline__ void cpasync16(uint32_t dst, const void* src) {
    asm volatile("cp.async.cg.shared.global [%0], [%1], 16;" :: "r"(dst), "l"(src));
}
#define CP_COMMIT() asm volatile("cp.async.commit_group;" ::: "memory")
#define CP_WAIT(n)  asm volatile("cp.async.wait_group %0;" :: "n"(n) : "memory")

__device__ __forceinline__ void ldsm4(uint32_t& r0, uint32_t& r1, uint32_t& r2, uint32_t& r3,
                                      uint32_t addr) {
    asm volatile("ldmatrix.sync.aligned.m8n8.x4.shared.b16 {%0,%1,%2,%3}, [%4];"
                 : "=r"(r0), "=r"(r1), "=r"(r2), "=r"(r3) : "r"(addr));
}
__device__ __forceinline__ void mma16816(float* c, uint32_t a0, uint32_t a1, uint32_t a2,
                                         uint32_t a3, uint32_t b0, uint32_t b1) {
    asm volatile(
        "mma.sync.aligned.m16n8k16.row.col.f32.f16.f16.f32 "
        "{%0,%1,%2,%3}, {%4,%5,%6,%7}, {%8,%9}, {%0,%1,%2,%3};"
        : "+f"(c[0]), "+f"(c[1]), "+f"(c[2]), "+f"(c[3])
        : "r"(a0), "r"(a1), "r"(a2), "r"(a3), "r"(b0), "r"(b1));
}
__device__ __forceinline__ uint32_t pack2h(float a, float b) {
    __half2 t = __floats2half2_rn(a, b);
    return *reinterpret_cast<uint32_t*>(&t);
}

// ------------------------- conversion kernels -------------------------
// fp32 -> fp16 rounding (no split)
__global__ void round_kernel(const float* __restrict__ in,
                             __half* __restrict__ hi, int n4) {
    int i = blockIdx.x * blockDim.x + threadIdx.x;
    if (i >= n4) return;
    float4 v = ((const float4*)in)[i];
    ((uint32_t*)hi)[2 * i]     = pack2h(v.x, v.y);
    ((uint32_t*)hi)[2 * i + 1] = pack2h(v.z, v.w);
}

// W [K, N] fp32 row-major -> Th [N, K] fp16 (transposed + rounded)
__global__ void transpose_round(const float* __restrict__ W,
                                __half* __restrict__ Th, int K, int N) {
    __shared__ float t[32][33];
    const int bx = blockIdx.x * 32;
    const int by = blockIdx.y * 32;
    const int x = threadIdx.x, y = threadIdx.y;
#pragma unroll
    for (int j = 0; j < 32; j += 8)
        t[y + j][x] = W[(size_t)(by + y + j) * N + bx + x];
    __syncthreads();
#pragma unroll
    for (int j = 0; j < 32; j += 8)
        Th[(size_t)(bx + y + j) * K + by + x] = __float2half_rn(t[x][y + j]);
}

// ===================== fp16 1-product GEMM, K-stage 64, 3-stage ring =====================
// C[8192, NTOT] = A[8192,1024] @ B[NTOT,1024]^T, fp32 accum.
// CTA tile 128x128; 256 thr = 8 warps (4M x 2N), warp 32x64. 2 CTAs/SM.
// EPI=1: scatter q(scaled)/k/v^T fp16. EPI=0: fp32 row-major store.
#define QK_ROWB 144                    // 128B data + 16B pad
#define QK_OFFB (128 * QK_ROWB)        // 18432 (B tile offset)
#define QK_STAGE (2 * 128 * QK_ROWB)   // 36864
#define QK_SMEM (3 * QK_STAGE)         // 110592
#define QK_NST 16                      // 1024 / 64

template <int NTOT, int EPI>
__global__ void __launch_bounds__(256, 2) mma_gemm(const __half* __restrict__ Ah_,
                                                   const __half* __restrict__ Bh_,
                                                   float* __restrict__ C) {
    extern __shared__ char sm[];
    const uint32_t sbase = smem_u32(sm);
    const int tid  = threadIdx.x;
    const int lane = tid & 31;
    const int wid  = tid >> 5;
    const int wm   = wid & 3;          // 0..3 (M blocks of 32)
    const int wn   = wid >> 2;         // 0..1 (N blocks of 64)
    const int row0 = blockIdx.y * 128;
    const int col0 = blockIdx.x * 128;

    float acc[2][8][4];
#pragma unroll
    for (int i = 0; i < 2; i++)
#pragma unroll
        for (int j = 0; j < 8; j++)
#pragma unroll
            for (int k = 0; k < 4; k++) acc[i][j][k] = 0.f;

    auto load_stage = [&](int kt, int buf) {
        const uint32_t sa = sbase + buf * QK_STAGE;
        const int kcol = kt * 64;
#pragma unroll
        for (int p = 0; p < 4; p++) {
            const int i = p * 256 + tid, r = i >> 3, c = i & 7;
            cpasync16(sa + r * QK_ROWB + c * 16,
                      Ah_ + (size_t)(row0 + r) * 1024 + kcol + c * 8);
            cpasync16(sa + QK_OFFB + r * QK_ROWB + c * 16,
                      Bh_ + (size_t)(col0 + r) * 1024 + kcol + c * 8);
        }
        CP_COMMIT();
    };

    const uint32_t a_base = (wm * 32 + (lane & 15)) * QK_ROWB + (lane >> 4) * 16;
    const uint32_t b_base = QK_OFFB +
        (wn * 64 + (lane & 7) + ((lane >> 4) << 3)) * QK_ROWB + ((lane >> 3) & 1) * 16;

    load_stage(0, 0);
    load_stage(1, 1);

    for (int kt = 0; kt < QK_NST; kt++) {
        if (kt == QK_NST - 1) { CP_WAIT(0); } else { CP_WAIT(1); }
        __syncthreads();
        if (kt + 2 < QK_NST) load_stage(kt + 2, (kt + 2) % 3);

        const uint32_t sa = sbase + (kt % 3) * QK_STAGE;
#pragma unroll
        for (int ks = 0; ks < 4; ks++) {
            const uint32_t koff = ks * 32;
            uint32_t ah[2][4], bh[8][2];
#pragma unroll
            for (int mt = 0; mt < 2; mt++)
                ldsm4(ah[mt][0], ah[mt][1], ah[mt][2], ah[mt][3],
                      sa + a_base + mt * 16 * QK_ROWB + koff);
#pragma unroll
            for (int p = 0; p < 4; p++)
                ldsm4(bh[2 * p][0], bh[2 * p][1], bh[2 * p + 1][0], bh[2 * p + 1][1],
                      sa + b_base + p * 16 * QK_ROWB + koff);
#pragma unroll
            for (int mt = 0; mt < 2; mt++)
#pragma unroll
                for (int nt = 0; nt < 8; nt++)
                    mma16816(acc[mt][nt], ah[mt][0], ah[mt][1], ah[mt][2], ah[mt][3],
                             bh[nt][0], bh[nt][1]);
        }
    }

    // epilogue
    const int rbase = lane >> 2;
    const int cpair = (lane & 3) * 2;
#pragma unroll
    for (int mt = 0; mt < 2; mt++) {
#pragma unroll
        for (int nt = 0; nt < 8; nt++) {
            const float* c = acc[mt][nt];
            const int gcol = col0 + wn * 64 + nt * 8 + cpair;
            const int r1 = row0 + wm * 32 + mt * 16 + rbase;
            if constexpr (EPI == 0) {
                *(float2*)&C[(size_t)r1 * NTOT + gcol]       = make_float2(c[0], c[1]);
                *(float2*)&C[(size_t)(r1 + 8) * NTOT + gcol] = make_float2(c[2], c[3]);
            } else {
                const int part = gcol >> 10;       // 0=Q 1=K 2=V
                const int rem  = gcol & 1023;
                const int h = rem >> 6, d = rem & 63;
#pragma unroll
                for (int hh = 0; hh < 2; hh++) {
                    const int gr = r1 + hh * 8;
                    const int b_ = gr >> 10, t_ = gr & 1023;
                    const float v0 = c[hh * 2], v1 = c[hh * 2 + 1];
                    if (part == 0) {
                        const size_t o = (((size_t)(b_ * N_HEAD + h)) * T_SEQ + t_) * DK + d;
                        *(uint32_t*)&g_qh[o] = pack2h(v0 * 0.125f, v1 * 0.125f);
                    } else if (part == 1) {
                        const size_t o = (((size_t)(b_ * N_HEAD + h)) * T_SEQ + t_) * DK + d;
                        *(uint32_t*)&g_kh[o] = pack2h(v0, v1);
                    } else {
                        const size_t o = (((size_t)(b_ * N_HEAD + h)) * DK + d) * T_SEQ + t_;
                        g_vth[o]         = __float2half_rn(v0);
                        g_vth[o + T_SEQ] = __float2half_rn(v1);
                    }
                }
            }
        }
    }
}

// ------------------------- tensor-core flash attention (fp16, 1-product S) ------------
#define AROWB 144
#define ATILE (64 * AROWB)           // 9216
#define AST_KH 0
#define AST_VH ATILE
#define ASTAGE (2 * ATILE)           // 18432
#define AQ_H (2 * ASTAGE)            // 36864
#define ATTN_SMEM (AQ_H + ATILE)     // 46080

__global__ void __launch_bounds__(128) attn_kernel() {
    extern __shared__ char sm[];
    const uint32_t sb = smem_u32(sm);
    const int tid  = threadIdx.x;
    const int lane = tid & 31;
    const int w    = tid >> 5;
    const int qt   = (int)gridDim.x - 1 - (int)blockIdx.x;  // long CTAs first
    const int bh   = blockIdx.y;

    const __half* Qh = g_qh + (size_t)bh * (T_SEQ * DK);
    const __half* Kh = g_kh + (size_t)bh * (T_SEQ * DK);
    const __half* Vh = g_vth + (size_t)bh * (DK * T_SEQ);

    auto load_kv = [&](int kt, int buf) {
        const uint32_t st = sb + buf * ASTAGE;
        const int t0 = kt * 64;
#pragma unroll
        for (int it = 0; it < 4; it++) {
            const int i = it * 128 + tid;
            const int r = i >> 3, c = i & 7;
            cpasync16(st + AST_KH + r * AROWB + c * 16, Kh + (size_t)(t0 + r) * DK + c * 8);
            cpasync16(st + AST_VH + r * AROWB + c * 16, Vh + (size_t)r * T_SEQ + t0 + c * 8);
        }
        CP_COMMIT();
    };

#pragma unroll
    for (int it = 0; it < 4; it++) {
        const int i = it * 128 + tid;
        const int r = i >> 3, c = i & 7;
        cpasync16(sb + AQ_H + r * AROWB + c * 16, Qh + (size_t)(qt * 64 + r) * DK + c * 8);
    }
    CP_COMMIT();
    load_kv(0, 0);

    CP_WAIT(1);
    __syncthreads();

    uint32_t qh[4][4];
    {
        const uint32_t qa = sb + AQ_H + (w * 16 + (lane & 15)) * AROWB + (lane >> 4) * 16;
#pragma unroll
        for (int ks = 0; ks < 4; ks++)
            ldsm4(qh[ks][0], qh[ks][1], qh[ks][2], qh[ks][3], qa + ks * 32);
    }

    float O[8][4];
#pragma unroll
    for (int i = 0; i < 8; i++)
#pragma unroll
        for (int j = 0; j < 4; j++) O[i][j] = 0.f;
    float m0 = -3.0e38f, m1 = -3.0e38f, l0 = 0.f, l1 = 0.f;

    const uint32_t bpat = ((lane & 7) + ((lane >> 4) << 3)) * AROWB + ((lane >> 3) & 1) * 16;

    for (int kt = 0; kt <= qt; kt++) {
        if (kt < qt) { load_kv(kt + 1, (kt + 1) & 1); CP_WAIT(1); } else { CP_WAIT(0); }
        __syncthreads();
        const uint32_t st = sb + (kt & 1) * ASTAGE;

        float S[8][4];
#pragma unroll
        for (int i = 0; i < 8; i++)
#pragma unroll
            for (int j = 0; j < 4; j++) S[i][j] = 0.f;

#pragma unroll
        for (int ks = 0; ks < 4; ks++) {
            uint32_t kh[8][2];
#pragma unroll
            for (int p = 0; p < 4; p++)
                ldsm4(kh[2 * p][0], kh[2 * p][1], kh[2 * p + 1][0], kh[2 * p + 1][1],
                      st + AST_KH + p * 16 * AROWB + bpat + ks * 32);
#pragma unroll
            for (int nt = 0; nt < 8; nt++)
                mma16816(S[nt], qh[ks][0], qh[ks][1], qh[ks][2], qh[ks][3], kh[nt][0], kh[nt][1]);
        }

        if (kt == qt) {
            const int grow = qt * 64 + w * 16 + (lane >> 2);
#pragma unroll
            for (int nt = 0; nt < 8; nt++) {
                const int col = qt * 64 + nt * 8 + (lane & 3) * 2;
                if (col     > grow)     S[nt][0] = -3.0e38f;
                if (col + 1 > grow)     S[nt][1] = -3.0e38f;
                if (col     > grow + 8) S[nt][2] = -3.0e38f;
                if (col + 1 > grow + 8) S[nt][3] = -3.0e38f;
            }
        }

        float mx0 = -3.0e38f, mx1 = -3.0e38f;
#pragma unroll
        for (int nt = 0; nt < 8; nt++) {
            mx0 = fmaxf(mx0, fmaxf(S[nt][0], S[nt][1]));
            mx1 = fmaxf(mx1, fmaxf(S[nt][2], S[nt][3]));
        }
        mx0 = fmaxf(mx0, __shfl_xor_sync(0xffffffffu, mx0, 1));
        mx0 = fmaxf(mx0, __shfl_xor_sync(0xffffffffu, mx0, 2));
        mx1 = fmaxf(mx1, __shfl_xor_sync(0xffffffffu, mx1, 1));
        mx1 = fmaxf(mx1, __shfl_xor_sync(0xffffffffu, mx1, 2));
        const float mn0 = fmaxf(m0, mx0);
        const float mn1 = fmaxf(m1, mx1);
        const float sc0 = __expf(m0 - mn0);
        const float sc1 = __expf(m1 - mn1);
        float sum0 = 0.f, sum1 = 0.f;
#pragma unroll
        for (int nt = 0; nt < 8; nt++) {
            S[nt][0] = __expf(S[nt][0] - mn0); sum0 += S[nt][0];
            S[nt][1] = __expf(S[nt][1] - mn0); sum0 += S[nt][1];
            S[nt][2] = __expf(S[nt][2] - mn1); sum1 += S[nt][2];
            S[nt][3] = __expf(S[nt][3] - mn1); sum1 += S[nt][3];
        }
        sum0 += __shfl_xor_sync(0xffffffffu, sum0, 1);
        sum0 += __shfl_xor_sync(0xffffffffu, sum0, 2);
        sum1 += __shfl_xor_sync(0xffffffffu, sum1, 1);
        sum1 += __shfl_xor_sync(0xffffffffu, sum1, 2);
        l0 = l0 * sc0 + sum0;
        l1 = l1 * sc1 + sum1;
        m0 = mn0; m1 = mn1;
#pragma unroll
        for (int nt = 0; nt < 8; nt++) {
            O[nt][0] *= sc0; O[nt][1] *= sc0;
            O[nt][2] *= sc1; O[nt][3] *= sc1;
        }

#pragma unroll
        for (int ks = 0; ks < 4; ks++) {
            uint32_t pa[4];
            pa[0] = pack2h(S[2 * ks][0],     S[2 * ks][1]);
            pa[1] = pack2h(S[2 * ks][2],     S[2 * ks][3]);
            pa[2] = pack2h(S[2 * ks + 1][0], S[2 * ks + 1][1]);
            pa[3] = pack2h(S[2 * ks + 1][2], S[2 * ks + 1][3]);
            uint32_t vh[8][2];
#pragma unroll
            for (int p = 0; p < 4; p++)
                ldsm4(vh[2 * p][0], vh[2 * p][1], vh[2 * p + 1][0], vh[2 * p + 1][1],
                      st + AST_VH + p * 16 * AROWB + bpat + ks * 32);
#pragma unroll
            for (int nt = 0; nt < 8; nt++)
                mma16816(O[nt], pa[0], pa[1], pa[2], pa[3], vh[nt][0], vh[nt][1]);
        }
        __syncthreads();
    }

    // ---- epilogue: y = O / l, fp16 single ----
    const float inv0 = 1.0f / l0;
    const float inv1 = 1.0f / l1;
    const int b_ = bh >> 4, h_ = bh & 15;
    const int t0 = qt * 64 + w * 16 + (lane >> 2);
#pragma unroll
    for (int nt = 0; nt < 8; nt++) {
        const int d = nt * 8 + (lane & 3) * 2;
        size_t o = ((size_t)(b_ * T_SEQ + t0)) * C_MODEL + h_ * DK + d;
        *(uint32_t*)&g_yh[o] = pack2h(O[nt][0] * inv0, O[nt][1] * inv0);
        o = ((size_t)(b_ * T_SEQ + t0 + 8)) * C_MODEL + h_ * DK + d;
        *(uint32_t*)&g_yh[o] = pack2h(O[nt][2] * inv1, O[nt][3] * inv1);
    }
}

// ---------------------------------------------------------------------------

extern "C" void kernel_launch(void* const* d_in, const int* in_sizes, int n_in,
                              void* d_out, int out_size) {
    const float* x     = (const float*)d_in[0];   // [8,1024,1024]
    const float* wqkv  = (const float*)d_in[1];   // [1024,3072]
    const float* wproj = (const float*)d_in[2];   // [1024,1024]
    float* out = (float*)d_out;                   // [8,1024,1024]

    cudaFuncSetAttribute(attn_kernel,
                         cudaFuncAttributeMaxDynamicSharedMemorySize, ATTN_SMEM);
    cudaFuncSetAttribute(mma_gemm<3072, 1>,
                         cudaFuncAttributeMaxDynamicSharedMemorySize, QK_SMEM);
    cudaFuncSetAttribute(mma_gemm<1024, 0>,
                         cudaFuncAttributeMaxDynamicSharedMemorySize, QK_SMEM);

    __half *xh, *yh, *wqh, *wph;
    cudaGetSymbolAddress((void**)&xh,  g_xh);
    cudaGetSymbolAddress((void**)&yh,  g_yh);
    cudaGetSymbolAddress((void**)&wqh, g_wqh);
    cudaGetSymbolAddress((void**)&wph, g_wph);

    // 1) conversions
    round_kernel<<<(M_ROWS * C_MODEL / 4 + 255) / 256, 256>>>(x, xh, M_ROWS * C_MODEL / 4);
    transpose_round<<<dim3(3072 / 32, 1024 / 32), dim3(32, 8)>>>(wqkv, wqh, 1024, 3072);
    transpose_round<<<dim3(1024 / 32, 1024 / 32), dim3(32, 8)>>>(wproj, wph, 1024, 1024);

    // 2) QKV projection (1-product) -> q(scaled)/k/v^T fp16
    mma_gemm<3072, 1><<<dim3(3072 / 128, M_ROWS / 128), 256, QK_SMEM>>>(xh, wqh, nullptr);

    // 3) tensor-core causal attention -> y fp16
    attn_kernel<<<dim3(T_SEQ / 64, N_BATCH * N_HEAD), 128, ATTN_SMEM>>>();

    // 4) output projection (1-product)
    mma_gemm<1024, 0><<<dim3(1024 / 128, M_ROWS / 128), 256, QK_SMEM>>>(yh, wph, out);
}